// round 10
// baseline (speedup 1.0000x reference)
#include <cuda_runtime.h>
#include <cuda_bf16.h>
#include <math.h>
#include <stdint.h>

// ---------------------------------------------------------------------------
// B=4, T=2048, C=1024.  out = softmax(causal(QK^T/32)) V Wo + bo
// mma.sync bf16 with bf16x3 split (hi*hi + lo*hi + hi*lo), fp32 accum.
// All operands pre-split to bf16 hi/lo in gmem; GEMM loop is cp.async-only.
// ---------------------------------------------------------------------------
#define BATCH 4
#define SEQ   2048
#define CH    1024
#define MTOT  (BATCH * SEQ)

typedef __nv_bfloat16 bf16;
typedef __nv_bfloat162 bf162;

__device__ bf16 g_xh[MTOT * CH], g_xl[MTOT * CH];
__device__ bf16 g_Wqh[CH * CH], g_Wql[CH * CH];
__device__ bf16 g_Wkh[CH * CH], g_Wkl[CH * CH];
__device__ bf16 g_Wvh[CH * CH], g_Wvl[CH * CH];
__device__ bf16 g_Woh[CH * CH], g_Wol[CH * CH];
__device__ bf16 g_Qh[MTOT * CH], g_Ql[MTOT * CH];
__device__ bf16 g_Kh[MTOT * CH], g_Kl[MTOT * CH];
__device__ bf16 g_Vh[MTOT * CH], g_Vl[MTOT * CH];
__device__ bf16 g_Oh[MTOT * CH], g_Ol[MTOT * CH];
__device__ float g_S[BATCH * SEQ * SEQ];
__device__ bf16 g_Ph[BATCH * SEQ * SEQ], g_Pl[BATCH * SEQ * SEQ];

#define TILE_M 128
#define TILE_N 128
#define BK     64
#define NTHREADS 256

// smem per stage: A (k-major, 128r x 64k, stride 144B) hi+lo;
// B k-major (128r x 64k, 144B) or n-major (64k x 128n, 272B) hi+lo.
#define AROW  144
#define AMAT  18432
#define OFF_AH 0
#define OFF_AL AMAT
#define OFF_BH (2 * AMAT)
#define STAGE  73728
#define NSTAGE 3
#define SMEM_TOTAL (NSTAGE * STAGE)   // 221184

__device__ __forceinline__ uint32_t smem_u32(const void* p) {
    uint32_t a;
    asm("{ .reg .u64 t; cvta.to.shared.u64 t, %1; cvt.u32.u64 %0, t; }" : "=r"(a) : "l"(p));
    return a;
}
#define CP16(dst, src) asm volatile("cp.async.cg.shared.global [%0], [%1], 16;" :: "r"(dst), "l"(src))
#define CP_COMMIT()    asm volatile("cp.async.commit_group;" ::: "memory")
#define CP_WAIT1()     asm volatile("cp.async.wait_group 1;" ::: "memory")

__device__ __forceinline__ void ldsm4(uint32_t* r, uint32_t addr) {
    asm volatile("ldmatrix.sync.aligned.m8n8.x4.shared.b16 {%0,%1,%2,%3}, [%4];"
                 : "=r"(r[0]), "=r"(r[1]), "=r"(r[2]), "=r"(r[3]) : "r"(addr));
}
__device__ __forceinline__ void ldsm4t(uint32_t* r, uint32_t addr) {
    asm volatile("ldmatrix.sync.aligned.m8n8.x4.trans.shared.b16 {%0,%1,%2,%3}, [%4];"
                 : "=r"(r[0]), "=r"(r[1]), "=r"(r[2]), "=r"(r[3]) : "r"(addr));
}
__device__ __forceinline__ void mma16816(float* d, const uint32_t* a, uint32_t b0, uint32_t b1) {
    asm volatile(
        "mma.sync.aligned.m16n8k16.row.col.f32.bf16.bf16.f32 "
        "{%0,%1,%2,%3},{%4,%5,%6,%7},{%8,%9},{%0,%1,%2,%3};"
        : "+f"(d[0]), "+f"(d[1]), "+f"(d[2]), "+f"(d[3])
        : "r"(a[0]), "r"(a[1]), "r"(a[2]), "r"(a[3]), "r"(b0), "r"(b1));
}
__device__ __forceinline__ void cvt_split(float x, bf16& h, bf16& l) {
    h = __float2bfloat16(x);
    l = __float2bfloat16(x - __bfloat162float(h));
}

// ---------------------------------------------------------------------------
__global__ void split_f32(const float* __restrict__ s, bf16* __restrict__ h,
                          bf16* __restrict__ l, int n)
{
    const int i = 4 * (blockIdx.x * blockDim.x + threadIdx.x);
    if (i >= n) return;
    float4 v = *reinterpret_cast<const float4*>(s + i);
    bf16 h0, l0, h1, l1, h2, l2, h3, l3;
    cvt_split(v.x, h0, l0); cvt_split(v.y, h1, l1);
    cvt_split(v.z, h2, l2); cvt_split(v.w, h3, l3);
    *reinterpret_cast<bf162*>(h + i)     = {h0, h1};
    *reinterpret_cast<bf162*>(h + i + 2) = {h2, h3};
    *reinterpret_cast<bf162*>(l + i)     = {l0, l1};
    *reinterpret_cast<bf162*>(l + i + 2) = {l2, l3};
}

// ---------------------------------------------------------------------------
// C = alpha * A @ op(B) (+bias) (+RoPE)
//  BN=false: B [N,K] k-major (non-trans ldmatrix).
//  BN=true : B [K,N] n-major (ldmatrix.trans).
//  EPI16: write hi/lo bf16 outputs; else fp32.
// ---------------------------------------------------------------------------
template<bool BN, bool ROPE, bool CSKIP, bool CKLIM, bool EPI16>
__global__ __launch_bounds__(NTHREADS, 1)
void gemm_bf3(const bf16* __restrict__ Ah, const bf16* __restrict__ Al,
              const bf16* __restrict__ Bh, const bf16* __restrict__ Bl,
              const float* __restrict__ bias,
              float* __restrict__ Cf, bf16* __restrict__ Ch, bf16* __restrict__ Cl,
              int M, int N, int K,
              long long sA, long long sB, long long sC, float alpha)
{
    constexpr int BMAT = BN ? 17408 : 18432;   // 64*272 or 128*144
    constexpr int BROW = BN ? 272 : 144;
    constexpr int OFF_BL = OFF_BH + BMAT;

    extern __shared__ __align__(256) char smem[];
    const uint32_t sbase = smem_u32(smem);

    const int m0 = blockIdx.y * TILE_M;
    const int n0 = blockIdx.x * TILE_N;
    if (CSKIP && n0 >= m0 + TILE_M) return;

    const bf16* Ahb = Ah + (long long)blockIdx.z * sA;
    const bf16* Alb = Al + (long long)blockIdx.z * sA;
    const bf16* Bhb = Bh + (long long)blockIdx.z * sB;
    const bf16* Blb = Bl + (long long)blockIdx.z * sB;

    const int tid = threadIdx.x;
    const int wid = tid >> 5;
    const int lid = tid & 31;
    const int warp_m = wid >> 2;
    const int warp_n = wid & 3;

    const int Kend  = CKLIM ? (m0 + TILE_M) : K;
    const int NITER = Kend / BK;

    float acc[4][4][4];
    #pragma unroll
    for (int i = 0; i < 4; i++)
        #pragma unroll
        for (int j = 0; j < 4; j++)
            #pragma unroll
            for (int k = 0; k < 4; k++) acc[i][j][k] = 0.f;

    auto issue = [&](int it) {
        if (it < NITER) {
            const uint32_t sb = sbase + (it % NSTAGE) * STAGE;
            const int kc = it * BK;
            #pragma unroll
            for (int i = 0; i < 4; ++i) {                 // A: 1024 16B chunks
                const int c  = tid + i * NTHREADS;
                const int r  = c >> 3;
                const int ch = c & 7;
                const size_t g = (size_t)(m0 + r) * K + kc + ch * 8;
                const uint32_t so = (uint32_t)(r * AROW + ch * 16);
                CP16(sb + OFF_AH + so, Ahb + g);
                CP16(sb + OFF_AL + so, Alb + g);
            }
            if (!BN) {
                #pragma unroll
                for (int i = 0; i < 4; ++i) {             // B k-major
                    const int c  = tid + i * NTHREADS;
                    const int r  = c >> 3;
                    const int ch = c & 7;
                    const size_t g = (size_t)(n0 + r) * K + kc + ch * 8;
                    const uint32_t so = (uint32_t)(r * BROW + ch * 16);
                    CP16(sb + OFF_BH + so, Bhb + g);
                    CP16(sb + OFF_BL + so, Blb + g);
                }
            } else {
                #pragma unroll
                for (int i = 0; i < 4; ++i) {             // B n-major: 64k x 128n
                    const int c  = tid + i * NTHREADS;
                    const int kr = c >> 4;
                    const int ch = c & 15;
                    const size_t g = (size_t)(kc + kr) * N + n0 + ch * 8;
                    const uint32_t so = (uint32_t)(kr * BROW + ch * 16);
                    CP16(sb + OFF_BH + so, Bhb + g);
                    CP16(sb + OFF_BL + so, Blb + g);
                }
            }
        }
        CP_COMMIT();
    };

    const int a_r = (lid & 15);
    const int a_c = (lid >> 4) << 3;
    const int b_r = (lid & 7) + ((lid >> 4) << 3);
    const int b_c = ((lid >> 3) & 1) << 3;
    const int t_k = (lid & 7) + (((lid >> 3) & 1) << 3);
    const int t_n = (lid >> 4) << 3;

    issue(0);
    issue(1);

    for (int it = 0; it < NITER; ++it) {
        CP_WAIT1();
        __syncthreads();
        // prefetch next stage FIRST (buffer (it+2)%3 == (it-1)%3, drained by
        // the barrier above), so gmem loads overlap the whole compute phase.
        issue(it + 2);
        const uint32_t sstage = sbase + (it % NSTAGE) * STAGE;

        #pragma unroll
        for (int kk = 0; kk < BK; kk += 16) {
            uint32_t ah[16], al[16], bh[8], bl[8];
            #pragma unroll
            for (int mt = 0; mt < 4; ++mt) {
                const uint32_t addr = sstage + OFF_AH +
                    (uint32_t)((warp_m * 64 + mt * 16 + a_r) * AROW + (kk + a_c) * 2);
                ldsm4(ah + mt * 4, addr);
                ldsm4(al + mt * 4, addr + AMAT);
            }
            if (!BN) {
                #pragma unroll
                for (int nt = 0; nt < 2; ++nt) {
                    const uint32_t addr = sstage + OFF_BH +
                        (uint32_t)((warp_n * 32 + nt * 16 + b_r) * BROW + (kk + b_c) * 2);
                    ldsm4(bh + nt * 4, addr);
                    ldsm4(bl + nt * 4, addr + BMAT);
                }
            } else {
                #pragma unroll
                for (int p = 0; p < 2; ++p) {
                    const uint32_t addr = sstage + OFF_BH +
                        (uint32_t)((kk + t_k) * BROW + (warp_n * 32 + p * 16 + t_n) * 2);
                    ldsm4t(bh + p * 4, addr);
                    ldsm4t(bl + p * 4, addr + BMAT);
                }
            }
            #pragma unroll
            for (int mt = 0; mt < 4; ++mt)
                #pragma unroll
                for (int nt = 0; nt < 4; ++nt) {
                    const uint32_t* bhp = &bh[(nt >> 1) * 4 + (nt & 1) * 2];
                    const uint32_t* blp = &bl[(nt >> 1) * 4 + (nt & 1) * 2];
                    mma16816(acc[mt][nt], ah + mt * 4, bhp[0], bhp[1]);
                    mma16816(acc[mt][nt], al + mt * 4, bhp[0], bhp[1]);
                    mma16816(acc[mt][nt], ah + mt * 4, blp[0], blp[1]);
                }
        }
    }

    // ---- epilogue ----
    const int mbase = m0 + warp_m * 64 + (lid >> 2);
    const int nbase = n0 + warp_n * 32 + (lid & 3) * 2;

    float binv[4];
    #pragma unroll
    for (int nt = 0; nt < 4; ++nt)
        if (ROPE) binv[nt] = powf(10000.0f, -(float)(nbase + nt * 8) / (float)N);

    #pragma unroll
    for (int mt = 0; mt < 4; ++mt) {
        #pragma unroll
        for (int h = 0; h < 2; ++h) {
            const int m = mbase + mt * 16 + h * 8;
            const int t = m & (SEQ - 1);
            #pragma unroll
            for (int nt = 0; nt < 4; ++nt) {
                const int n = nbase + nt * 8;
                float v0 = acc[mt][nt][h * 2 + 0] * alpha;
                float v1 = acc[mt][nt][h * 2 + 1] * alpha;
                if (bias) { v0 += bias[n]; v1 += bias[n + 1]; }
                if (ROPE) {
                    float s, co;
                    sincosf((float)t * binv[nt], &s, &co);
                    const float x0 = v0, x1 = v1;
                    v0 = x0 * co - x1 * s;
                    v1 = x1 * co + x0 * s;
                }
                const size_t off = (size_t)m * N + n + (size_t)blockIdx.z * sC;
                if (EPI16) {
                    bf16 h0, l0, h1, l1;
                    cvt_split(v0, h0, l0); cvt_split(v1, h1, l1);
                    *reinterpret_cast<bf162*>(Ch + off) = {h0, h1};
                    *reinterpret_cast<bf162*>(Cl + off) = {l0, l1};
                } else {
                    *reinterpret_cast<float2*>(Cf + off) = make_float2(v0, v1);
                }
            }
        }
    }
}

// ---------------------------------------------------------------------------
// Causal softmax: fp32 S row -> hi/lo bf16 P row; zero-fills to 128 boundary.
// ---------------------------------------------------------------------------
__global__ __launch_bounds__(256)
void softmax_split(float* __restrict__ S, bf16* __restrict__ Ph,
                   bf16* __restrict__ Pl, int T)
{
    const long long row = blockIdx.x;
    const int t = (int)(row % T);
    float* s = S + row * (long long)T;
    bf16* ph = Ph + row * (long long)T;
    bf16* pl = Pl + row * (long long)T;
    const int len  = t + 1;
    const int zlim = ((t >> 7) + 1) << 7;
    const int tid = threadIdx.x;

    __shared__ float sh[8];
    __shared__ float bcast;

    float mx = -3.0e38f;
    for (int i = tid; i < len; i += 256) mx = fmaxf(mx, s[i]);
    #pragma unroll
    for (int o = 16; o > 0; o >>= 1) mx = fmaxf(mx, __shfl_xor_sync(0xffffffffu, mx, o));
    if ((tid & 31) == 0) sh[tid >> 5] = mx;
    __syncthreads();
    if (tid == 0) {
        float m = sh[0];
        #pragma unroll
        for (int i = 1; i < 8; i++) m = fmaxf(m, sh[i]);
        bcast = m;
    }
    __syncthreads();
    mx = bcast;

    float sum = 0.f;
    for (int i = tid; i < len; i += 256) {
        float e = expf(s[i] - mx);
        s[i] = e;
        sum += e;
    }
    #pragma unroll
    for (int o = 16; o > 0; o >>= 1) sum += __shfl_xor_sync(0xffffffffu, sum, o);
    __syncthreads();
    if ((tid & 31) == 0) sh[tid >> 5] = sum;
    __syncthreads();
    if (tid == 0) {
        float acc = 0.f;
        #pragma unroll
        for (int i = 0; i < 8; i++) acc += sh[i];
        bcast = acc;
    }
    __syncthreads();
    const float invs = 1.0f / bcast;

    for (int i = tid; i < len; i += 256) {
        bf16 h, l;
        cvt_split(s[i] * invs, h, l);
        ph[i] = h; pl[i] = l;
    }
    const bf16 z = __float2bfloat16(0.f);
    for (int i = len + tid; i < zlim; i += 256) { ph[i] = z; pl[i] = z; }
}

// ---------------------------------------------------------------------------
// kernel_launch: x, Wq, bq, Wk, bk, Wv, bv, Wo, bo
// ---------------------------------------------------------------------------
extern "C" void kernel_launch(void* const* d_in, const int* in_sizes, int n_in,
                              void* d_out, int out_size)
{
    const float* x  = (const float*)d_in[0];
    const float* Wq = (const float*)d_in[1];
    const float* bq = (const float*)d_in[2];
    const float* Wk = (const float*)d_in[3];
    const float* bk = (const float*)d_in[4];
    const float* Wv = (const float*)d_in[5];
    const float* bv = (const float*)d_in[6];
    const float* Wo = (const float*)d_in[7];
    const float* bo = (const float*)d_in[8];
    float* out = (float*)d_out;

    bf16 *xh, *xl, *Wqh, *Wql, *Wkh, *Wkl, *Wvh, *Wvl, *Woh, *Wol;
    bf16 *Qh, *Ql, *Kh, *Kl, *Vh, *Vl, *Oh, *Ol, *Ph, *Pl;
    float* pS;
    cudaGetSymbolAddress((void**)&xh, g_xh);   cudaGetSymbolAddress((void**)&xl, g_xl);
    cudaGetSymbolAddress((void**)&Wqh, g_Wqh); cudaGetSymbolAddress((void**)&Wql, g_Wql);
    cudaGetSymbolAddress((void**)&Wkh, g_Wkh); cudaGetSymbolAddress((void**)&Wkl, g_Wkl);
    cudaGetSymbolAddress((void**)&Wvh, g_Wvh); cudaGetSymbolAddress((void**)&Wvl, g_Wvl);
    cudaGetSymbolAddress((void**)&Woh, g_Woh); cudaGetSymbolAddress((void**)&Wol, g_Wol);
    cudaGetSymbolAddress((void**)&Qh, g_Qh);   cudaGetSymbolAddress((void**)&Ql, g_Ql);
    cudaGetSymbolAddress((void**)&Kh, g_Kh);   cudaGetSymbolAddress((void**)&Kl, g_Kl);
    cudaGetSymbolAddress((void**)&Vh, g_Vh);   cudaGetSymbolAddress((void**)&Vl, g_Vl);
    cudaGetSymbolAddress((void**)&Oh, g_Oh);   cudaGetSymbolAddress((void**)&Ol, g_Ol);
    cudaGetSymbolAddress((void**)&Ph, g_Ph);   cudaGetSymbolAddress((void**)&Pl, g_Pl);
    cudaGetSymbolAddress((void**)&pS, g_S);

    const int B = BATCH, T = SEQ, C = CH, M = MTOT;
    const long long sTC = (long long)T * C;
    const long long sTT = (long long)T * T;

    cudaFuncSetAttribute(gemm_bf3<true,  true,  false, false, true >, cudaFuncAttributeMaxDynamicSharedMemorySize, SMEM_TOTAL);
    cudaFuncSetAttribute(gemm_bf3<true,  false, false, false, true >, cudaFuncAttributeMaxDynamicSharedMemorySize, SMEM_TOTAL);
    cudaFuncSetAttribute(gemm_bf3<false, false, true,  false, false>, cudaFuncAttributeMaxDynamicSharedMemorySize, SMEM_TOTAL);
    cudaFuncSetAttribute(gemm_bf3<true,  false, false, true,  true >, cudaFuncAttributeMaxDynamicSharedMemorySize, SMEM_TOTAL);
    cudaFuncSetAttribute(gemm_bf3<true,  false, false, false, false>, cudaFuncAttributeMaxDynamicSharedMemorySize, SMEM_TOTAL);

    split_f32<<<(M * C / 4 + 255) / 256, 256>>>(x, xh, xl, M * C);
    split_f32<<<(C * C / 4 + 255) / 256, 256>>>(Wq, Wqh, Wql, C * C);
    split_f32<<<(C * C / 4 + 255) / 256, 256>>>(Wk, Wkh, Wkl, C * C);
    split_f32<<<(C * C / 4 + 255) / 256, 256>>>(Wv, Wvh, Wvl, C * C);
    split_f32<<<(C * C / 4 + 255) / 256, 256>>>(Wo, Woh, Wol, C * C);

    dim3 blk(NTHREADS);
    dim3 gridProj(C / TILE_N, M / TILE_M, 1);
    dim3 gridS(T / TILE_N, T / TILE_M, B);
    dim3 gridPV(C / TILE_N, T / TILE_M, B);

    gemm_bf3<true, true,  false, false, true><<<gridProj, blk, SMEM_TOTAL>>>(
        xh, xl, Wqh, Wql, bq, nullptr, Qh, Ql, M, C, C, 0, 0, 0, 1.0f);
    gemm_bf3<true, true,  false, false, true><<<gridProj, blk, SMEM_TOTAL>>>(
        xh, xl, Wkh, Wkl, bk, nullptr, Kh, Kl, M, C, C, 0, 0, 0, 1.0f);
    gemm_bf3<true, false, false, false, true><<<gridProj, blk, SMEM_TOTAL>>>(
        xh, xl, Wvh, Wvl, bv, nullptr, Vh, Vl, M, C, C, 0, 0, 0, 1.0f);

    gemm_bf3<false, false, true, false, false><<<gridS, blk, SMEM_TOTAL>>>(
        Qh, Ql, Kh, Kl, nullptr, pS, nullptr, nullptr, T, T, C, sTC, sTC, sTT, 0.03125f);

    softmax_split<<<B * T, blk>>>(pS, Ph, Pl, T);

    gemm_bf3<true, false, false, true, true><<<gridPV, blk, SMEM_TOTAL>>>(
        Ph, Pl, Vh, Vl, nullptr, nullptr, Oh, Ol, T, C, T, sTT, sTC, sTC, 1.0f);

    gemm_bf3<true, false, false, false, false><<<gridProj, blk, SMEM_TOTAL>>>(
        Oh, Ol, Woh, Wol, bo, out, nullptr, nullptr, M, C, C, 0, 0, 0, 1.0f);
}

// round 11
// speedup vs baseline: 1.0063x; 1.0063x over previous
#include <cuda_runtime.h>
#include <cuda_bf16.h>
#include <math.h>
#include <stdint.h>

// ---------------------------------------------------------------------------
// B=4, T=2048, C=1024.  out = softmax(causal(QK^T/32)) V Wo + bo
// mma.sync bf16 with bf16x3 split (hi*hi + lo*hi + hi*lo), fp32 accum.
// 512 threads / 16 warps per CTA (4 warps/SMSP) for HMMA latency hiding.
// ---------------------------------------------------------------------------
#define BATCH 4
#define SEQ   2048
#define CH    1024
#define MTOT  (BATCH * SEQ)

typedef __nv_bfloat16 bf16;
typedef __nv_bfloat162 bf162;

__device__ bf16 g_xh[MTOT * CH], g_xl[MTOT * CH];
__device__ bf16 g_Wqh[CH * CH], g_Wql[CH * CH];
__device__ bf16 g_Wkh[CH * CH], g_Wkl[CH * CH];
__device__ bf16 g_Wvh[CH * CH], g_Wvl[CH * CH];
__device__ bf16 g_Woh[CH * CH], g_Wol[CH * CH];
__device__ bf16 g_Qh[MTOT * CH], g_Ql[MTOT * CH];
__device__ bf16 g_Kh[MTOT * CH], g_Kl[MTOT * CH];
__device__ bf16 g_Vh[MTOT * CH], g_Vl[MTOT * CH];
__device__ bf16 g_Oh[MTOT * CH], g_Ol[MTOT * CH];
__device__ float g_S[BATCH * SEQ * SEQ];
__device__ bf16 g_Ph[BATCH * SEQ * SEQ], g_Pl[BATCH * SEQ * SEQ];

#define TILE_M 128
#define TILE_N 128
#define BK     64
#define NTHREADS 512

// smem per stage: A (k-major, 128r x 64k, stride 144B) hi+lo;
// B k-major (128r x 64k, 144B) or n-major (64k x 128n, 272B) hi+lo.
#define AROW  144
#define AMAT  18432
#define OFF_AH 0
#define OFF_AL AMAT
#define OFF_BH (2 * AMAT)
#define STAGE  73728
#define NSTAGE 3
#define SMEM_TOTAL (NSTAGE * STAGE)   // 221184

__device__ __forceinline__ uint32_t smem_u32(const void* p) {
    uint32_t a;
    asm("{ .reg .u64 t; cvta.to.shared.u64 t, %1; cvt.u32.u64 %0, t; }" : "=r"(a) : "l"(p));
    return a;
}
#define CP16(dst, src) asm volatile("cp.async.cg.shared.global [%0], [%1], 16;" :: "r"(dst), "l"(src))
#define CP_COMMIT()    asm volatile("cp.async.commit_group;" ::: "memory")
#define CP_WAIT1()     asm volatile("cp.async.wait_group 1;" ::: "memory")

__device__ __forceinline__ void ldsm4(uint32_t* r, uint32_t addr) {
    asm volatile("ldmatrix.sync.aligned.m8n8.x4.shared.b16 {%0,%1,%2,%3}, [%4];"
                 : "=r"(r[0]), "=r"(r[1]), "=r"(r[2]), "=r"(r[3]) : "r"(addr));
}
__device__ __forceinline__ void ldsm4t(uint32_t* r, uint32_t addr) {
    asm volatile("ldmatrix.sync.aligned.m8n8.x4.trans.shared.b16 {%0,%1,%2,%3}, [%4];"
                 : "=r"(r[0]), "=r"(r[1]), "=r"(r[2]), "=r"(r[3]) : "r"(addr));
}
__device__ __forceinline__ void mma16816(float* d, const uint32_t* a, uint32_t b0, uint32_t b1) {
    asm volatile(
        "mma.sync.aligned.m16n8k16.row.col.f32.bf16.bf16.f32 "
        "{%0,%1,%2,%3},{%4,%5,%6,%7},{%8,%9},{%0,%1,%2,%3};"
        : "+f"(d[0]), "+f"(d[1]), "+f"(d[2]), "+f"(d[3])
        : "r"(a[0]), "r"(a[1]), "r"(a[2]), "r"(a[3]), "r"(b0), "r"(b1));
}
__device__ __forceinline__ void cvt_split(float x, bf16& h, bf16& l) {
    h = __float2bfloat16(x);
    l = __float2bfloat16(x - __bfloat162float(h));
}

// ---------------------------------------------------------------------------
__global__ void split_f32(const float* __restrict__ s, bf16* __restrict__ h,
                          bf16* __restrict__ l, int n)
{
    const int i = 4 * (blockIdx.x * blockDim.x + threadIdx.x);
    if (i >= n) return;
    float4 v = *reinterpret_cast<const float4*>(s + i);
    bf16 h0, l0, h1, l1, h2, l2, h3, l3;
    cvt_split(v.x, h0, l0); cvt_split(v.y, h1, l1);
    cvt_split(v.z, h2, l2); cvt_split(v.w, h3, l3);
    *reinterpret_cast<bf162*>(h + i)     = {h0, h1};
    *reinterpret_cast<bf162*>(h + i + 2) = {h2, h3};
    *reinterpret_cast<bf162*>(l + i)     = {l0, l1};
    *reinterpret_cast<bf162*>(l + i + 2) = {l2, l3};
}

// ---------------------------------------------------------------------------
// C = alpha * A @ op(B) (+bias) (+RoPE)
//  BN=false: B [N,K] k-major (non-trans ldmatrix).
//  BN=true : B [K,N] n-major (ldmatrix.trans).
//  EPI16: write hi/lo bf16 outputs; else fp32.
// 16 warps: warp (warp_m, warp_n) in 4x4 grid, warptile 32x32.
// ---------------------------------------------------------------------------
template<bool BN, bool ROPE, bool CSKIP, bool CKLIM, bool EPI16>
__global__ __launch_bounds__(NTHREADS, 1)
void gemm_bf3(const bf16* __restrict__ Ah, const bf16* __restrict__ Al,
              const bf16* __restrict__ Bh, const bf16* __restrict__ Bl,
              const float* __restrict__ bias,
              float* __restrict__ Cf, bf16* __restrict__ Ch, bf16* __restrict__ Cl,
              int M, int N, int K,
              long long sA, long long sB, long long sC, float alpha)
{
    constexpr int BMAT = BN ? 17408 : 18432;   // 64*272 or 128*144
    constexpr int BROW = BN ? 272 : 144;
    constexpr int OFF_BL = OFF_BH + BMAT;

    extern __shared__ __align__(256) char smem[];
    const uint32_t sbase = smem_u32(smem);

    const int m0 = blockIdx.y * TILE_M;
    const int n0 = blockIdx.x * TILE_N;
    if (CSKIP && n0 >= m0 + TILE_M) return;

    const bf16* Ahb = Ah + (long long)blockIdx.z * sA;
    const bf16* Alb = Al + (long long)blockIdx.z * sA;
    const bf16* Bhb = Bh + (long long)blockIdx.z * sB;
    const bf16* Blb = Bl + (long long)blockIdx.z * sB;

    const int tid = threadIdx.x;
    const int wid = tid >> 5;
    const int lid = tid & 31;
    const int warp_m = wid >> 2;      // 0..3 -> 32-row slab
    const int warp_n = wid & 3;       // 0..3 -> 32-col slab

    const int Kend  = CKLIM ? (m0 + TILE_M) : K;
    const int NITER = Kend / BK;

    float acc[2][4][4];
    #pragma unroll
    for (int i = 0; i < 2; i++)
        #pragma unroll
        for (int j = 0; j < 4; j++)
            #pragma unroll
            for (int k = 0; k < 4; k++) acc[i][j][k] = 0.f;

    auto issue = [&](int it) {
        if (it < NITER) {
            const uint32_t sb = sbase + (it % NSTAGE) * STAGE;
            const int kc = it * BK;
            #pragma unroll
            for (int i = 0; i < 2; ++i) {                 // A: 1024 16B chunks
                const int c  = tid + i * NTHREADS;
                const int r  = c >> 3;
                const int ch = c & 7;
                const size_t g = (size_t)(m0 + r) * K + kc + ch * 8;
                const uint32_t so = (uint32_t)(r * AROW + ch * 16);
                CP16(sb + OFF_AH + so, Ahb + g);
                CP16(sb + OFF_AL + so, Alb + g);
            }
            if (!BN) {
                #pragma unroll
                for (int i = 0; i < 2; ++i) {             // B k-major
                    const int c  = tid + i * NTHREADS;
                    const int r  = c >> 3;
                    const int ch = c & 7;
                    const size_t g = (size_t)(n0 + r) * K + kc + ch * 8;
                    const uint32_t so = (uint32_t)(r * BROW + ch * 16);
                    CP16(sb + OFF_BH + so, Bhb + g);
                    CP16(sb + OFF_BL + so, Blb + g);
                }
            } else {
                #pragma unroll
                for (int i = 0; i < 2; ++i) {             // B n-major: 64k x 128n
                    const int c  = tid + i * NTHREADS;
                    const int kr = c >> 4;
                    const int ch = c & 15;
                    const size_t g = (size_t)(kc + kr) * N + n0 + ch * 8;
                    const uint32_t so = (uint32_t)(kr * BROW + ch * 16);
                    CP16(sb + OFF_BH + so, Bhb + g);
                    CP16(sb + OFF_BL + so, Blb + g);
                }
            }
        }
        CP_COMMIT();
    };

    // ldmatrix lane mappings (these make quad order {k0-7, k8-15} per n-block)
    const int a_r = (lid & 15);
    const int a_c = (lid >> 4) << 3;
    const int b_r = (lid & 7) + ((lid >> 4) << 3);
    const int b_c = ((lid >> 3) & 1) << 3;
    const int t_k = (lid & 7) + (((lid >> 3) & 1) << 3);
    const int t_n = (lid >> 4) << 3;

    issue(0);
    issue(1);

    for (int it = 0; it < NITER; ++it) {
        CP_WAIT1();
        __syncthreads();
        issue(it + 2);   // prefetch into drained buffer, overlaps compute
        const uint32_t sstage = sbase + (it % NSTAGE) * STAGE;

        #pragma unroll
        for (int kk = 0; kk < BK; kk += 16) {
            uint32_t ah[8], al[8], bh[8], bl[8];
            #pragma unroll
            for (int mt = 0; mt < 2; ++mt) {
                const uint32_t addr = sstage + OFF_AH +
                    (uint32_t)((warp_m * 32 + mt * 16 + a_r) * AROW + (kk + a_c) * 2);
                ldsm4(ah + mt * 4, addr);
                ldsm4(al + mt * 4, addr + AMAT);
            }
            if (!BN) {
                #pragma unroll
                for (int nt = 0; nt < 2; ++nt) {
                    const uint32_t addr = sstage + OFF_BH +
                        (uint32_t)((warp_n * 32 + nt * 16 + b_r) * BROW + (kk + b_c) * 2);
                    ldsm4(bh + nt * 4, addr);
                    ldsm4(bl + nt * 4, addr + BMAT);
                }
            } else {
                #pragma unroll
                for (int p = 0; p < 2; ++p) {
                    const uint32_t addr = sstage + OFF_BH +
                        (uint32_t)((kk + t_k) * BROW + (warp_n * 32 + p * 16 + t_n) * 2);
                    ldsm4t(bh + p * 4, addr);
                    ldsm4t(bl + p * 4, addr + BMAT);
                }
            }
            #pragma unroll
            for (int mt = 0; mt < 2; ++mt)
                #pragma unroll
                for (int nt = 0; nt < 4; ++nt) {
                    const uint32_t* bhp = &bh[(nt >> 1) * 4 + (nt & 1) * 2];
                    const uint32_t* blp = &bl[(nt >> 1) * 4 + (nt & 1) * 2];
                    mma16816(acc[mt][nt], ah + mt * 4, bhp[0], bhp[1]);
                    mma16816(acc[mt][nt], al + mt * 4, bhp[0], bhp[1]);
                    mma16816(acc[mt][nt], ah + mt * 4, blp[0], blp[1]);
                }
        }
    }

    // ---- epilogue ----
    const int mbase = m0 + warp_m * 32 + (lid >> 2);
    const int nbase = n0 + warp_n * 32 + (lid & 3) * 2;

    float binv[4];
    #pragma unroll
    for (int nt = 0; nt < 4; ++nt)
        if (ROPE) binv[nt] = powf(10000.0f, -(float)(nbase + nt * 8) / (float)N);

    #pragma unroll
    for (int mt = 0; mt < 2; ++mt) {
        #pragma unroll
        for (int h = 0; h < 2; ++h) {
            const int m = mbase + mt * 16 + h * 8;
            const int t = m & (SEQ - 1);
            #pragma unroll
            for (int nt = 0; nt < 4; ++nt) {
                const int n = nbase + nt * 8;
                float v0 = acc[mt][nt][h * 2 + 0] * alpha;
                float v1 = acc[mt][nt][h * 2 + 1] * alpha;
                if (bias) { v0 += bias[n]; v1 += bias[n + 1]; }
                if (ROPE) {
                    float s, co;
                    sincosf((float)t * binv[nt], &s, &co);
                    const float x0 = v0, x1 = v1;
                    v0 = x0 * co - x1 * s;
                    v1 = x1 * co + x0 * s;
                }
                const size_t off = (size_t)m * N + n + (size_t)blockIdx.z * sC;
                if (EPI16) {
                    bf16 h0, l0, h1, l1;
                    cvt_split(v0, h0, l0); cvt_split(v1, h1, l1);
                    *reinterpret_cast<bf162*>(Ch + off) = {h0, h1};
                    *reinterpret_cast<bf162*>(Cl + off) = {l0, l1};
                } else {
                    *reinterpret_cast<float2*>(Cf + off) = make_float2(v0, v1);
                }
            }
        }
    }
}

// ---------------------------------------------------------------------------
// Causal softmax: fp32 S row -> hi/lo bf16 P row; zero-fills to 128 boundary.
// ---------------------------------------------------------------------------
__global__ __launch_bounds__(256)
void softmax_split(float* __restrict__ S, bf16* __restrict__ Ph,
                   bf16* __restrict__ Pl, int T)
{
    const long long row = blockIdx.x;
    const int t = (int)(row % T);
    float* s = S + row * (long long)T;
    bf16* ph = Ph + row * (long long)T;
    bf16* pl = Pl + row * (long long)T;
    const int len  = t + 1;
    const int zlim = ((t >> 7) + 1) << 7;
    const int tid = threadIdx.x;

    __shared__ float sh[8];
    __shared__ float bcast;

    float mx = -3.0e38f;
    for (int i = tid; i < len; i += 256) mx = fmaxf(mx, s[i]);
    #pragma unroll
    for (int o = 16; o > 0; o >>= 1) mx = fmaxf(mx, __shfl_xor_sync(0xffffffffu, mx, o));
    if ((tid & 31) == 0) sh[tid >> 5] = mx;
    __syncthreads();
    if (tid == 0) {
        float m = sh[0];
        #pragma unroll
        for (int i = 1; i < 8; i++) m = fmaxf(m, sh[i]);
        bcast = m;
    }
    __syncthreads();
    mx = bcast;

    float sum = 0.f;
    for (int i = tid; i < len; i += 256) {
        float e = expf(s[i] - mx);
        s[i] = e;
        sum += e;
    }
    #pragma unroll
    for (int o = 16; o > 0; o >>= 1) sum += __shfl_xor_sync(0xffffffffu, sum, o);
    __syncthreads();
    if ((tid & 31) == 0) sh[tid >> 5] = sum;
    __syncthreads();
    if (tid == 0) {
        float acc = 0.f;
        #pragma unroll
        for (int i = 0; i < 8; i++) acc += sh[i];
        bcast = acc;
    }
    __syncthreads();
    const float invs = 1.0f / bcast;

    for (int i = tid; i < len; i += 256) {
        bf16 h, l;
        cvt_split(s[i] * invs, h, l);
        ph[i] = h; pl[i] = l;
    }
    const bf16 z = __float2bfloat16(0.f);
    for (int i = len + tid; i < zlim; i += 256) { ph[i] = z; pl[i] = z; }
}

// ---------------------------------------------------------------------------
// kernel_launch: x, Wq, bq, Wk, bk, Wv, bv, Wo, bo
// ---------------------------------------------------------------------------
extern "C" void kernel_launch(void* const* d_in, const int* in_sizes, int n_in,
                              void* d_out, int out_size)
{
    const float* x  = (const float*)d_in[0];
    const float* Wq = (const float*)d_in[1];
    const float* bq = (const float*)d_in[2];
    const float* Wk = (const float*)d_in[3];
    const float* bk = (const float*)d_in[4];
    const float* Wv = (const float*)d_in[5];
    const float* bv = (const float*)d_in[6];
    const float* Wo = (const float*)d_in[7];
    const float* bo = (const float*)d_in[8];
    float* out = (float*)d_out;

    bf16 *xh, *xl, *Wqh, *Wql, *Wkh, *Wkl, *Wvh, *Wvl, *Woh, *Wol;
    bf16 *Qh, *Ql, *Kh, *Kl, *Vh, *Vl, *Oh, *Ol, *Ph, *Pl;
    float* pS;
    cudaGetSymbolAddress((void**)&xh, g_xh);   cudaGetSymbolAddress((void**)&xl, g_xl);
    cudaGetSymbolAddress((void**)&Wqh, g_Wqh); cudaGetSymbolAddress((void**)&Wql, g_Wql);
    cudaGetSymbolAddress((void**)&Wkh, g_Wkh); cudaGetSymbolAddress((void**)&Wkl, g_Wkl);
    cudaGetSymbolAddress((void**)&Wvh, g_Wvh); cudaGetSymbolAddress((void**)&Wvl, g_Wvl);
    cudaGetSymbolAddress((void**)&Woh, g_Woh); cudaGetSymbolAddress((void**)&Wol, g_Wol);
    cudaGetSymbolAddress((void**)&Qh, g_Qh);   cudaGetSymbolAddress((void**)&Ql, g_Ql);
    cudaGetSymbolAddress((void**)&Kh, g_Kh);   cudaGetSymbolAddress((void**)&Kl, g_Kl);
    cudaGetSymbolAddress((void**)&Vh, g_Vh);   cudaGetSymbolAddress((void**)&Vl, g_Vl);
    cudaGetSymbolAddress((void**)&Oh, g_Oh);   cudaGetSymbolAddress((void**)&Ol, g_Ol);
    cudaGetSymbolAddress((void**)&Ph, g_Ph);   cudaGetSymbolAddress((void**)&Pl, g_Pl);
    cudaGetSymbolAddress((void**)&pS, g_S);

    const int B = BATCH, T = SEQ, C = CH, M = MTOT;
    const long long sTC = (long long)T * C;
    const long long sTT = (long long)T * T;

    cudaFuncSetAttribute(gemm_bf3<true,  true,  false, false, true >, cudaFuncAttributeMaxDynamicSharedMemorySize, SMEM_TOTAL);
    cudaFuncSetAttribute(gemm_bf3<true,  false, false, false, true >, cudaFuncAttributeMaxDynamicSharedMemorySize, SMEM_TOTAL);
    cudaFuncSetAttribute(gemm_bf3<false, false, true,  false, false>, cudaFuncAttributeMaxDynamicSharedMemorySize, SMEM_TOTAL);
    cudaFuncSetAttribute(gemm_bf3<true,  false, false, true,  true >, cudaFuncAttributeMaxDynamicSharedMemorySize, SMEM_TOTAL);
    cudaFuncSetAttribute(gemm_bf3<true,  false, false, false, false>, cudaFuncAttributeMaxDynamicSharedMemorySize, SMEM_TOTAL);

    split_f32<<<(M * C / 4 + 255) / 256, 256>>>(x, xh, xl, M * C);
    split_f32<<<(C * C / 4 + 255) / 256, 256>>>(Wq, Wqh, Wql, C * C);
    split_f32<<<(C * C / 4 + 255) / 256, 256>>>(Wk, Wkh, Wkl, C * C);
    split_f32<<<(C * C / 4 + 255) / 256, 256>>>(Wv, Wvh, Wvl, C * C);
    split_f32<<<(C * C / 4 + 255) / 256, 256>>>(Wo, Woh, Wol, C * C);

    dim3 blk(NTHREADS);
    dim3 gridProj(C / TILE_N, M / TILE_M, 1);
    dim3 gridS(T / TILE_N, T / TILE_M, B);
    dim3 gridPV(C / TILE_N, T / TILE_M, B);

    gemm_bf3<true, true,  false, false, true><<<gridProj, blk, SMEM_TOTAL>>>(
        xh, xl, Wqh, Wql, bq, nullptr, Qh, Ql, M, C, C, 0, 0, 0, 1.0f);
    gemm_bf3<true, true,  false, false, true><<<gridProj, blk, SMEM_TOTAL>>>(
        xh, xl, Wkh, Wkl, bk, nullptr, Kh, Kl, M, C, C, 0, 0, 0, 1.0f);
    gemm_bf3<true, false, false, false, true><<<gridProj, blk, SMEM_TOTAL>>>(
        xh, xl, Wvh, Wvl, bv, nullptr, Vh, Vl, M, C, C, 0, 0, 0, 1.0f);

    gemm_bf3<false, false, true, false, false><<<gridS, blk, SMEM_TOTAL>>>(
        Qh, Ql, Kh, Kl, nullptr, pS, nullptr, nullptr, T, T, C, sTC, sTC, sTT, 0.03125f);

    softmax_split<<<B * T, 256>>>(pS, Ph, Pl, T);

    gemm_bf3<true, false, false, true, true><<<gridPV, blk, SMEM_TOTAL>>>(
        Ph, Pl, Vh, Vl, nullptr, nullptr, Oh, Ol, T, C, T, sTT, sTC, sTC, 1.0f);

    gemm_bf3<true, false, false, false, false><<<gridProj, blk, SMEM_TOTAL>>>(
        Oh, Ol, Woh, Wol, bo, out, nullptr, nullptr, M, C, C, 0, 0, 0, 1.0f);
}

// round 12
// speedup vs baseline: 1.3559x; 1.3473x over previous
#include <cuda_runtime.h>
#include <cuda_fp16.h>
#include <math.h>
#include <stdint.h>

// ---------------------------------------------------------------------------
// B=4, T=2048, C=1024.  out = softmax(causal(QK^T/32)) V Wo + bo
// mma.sync fp16 (fp32 accum). A-side operands split fp16 hi+lo (2 MMAs/k16:
// Ah*Bh + Al*Bh); B-side (weights, K, V) single fp16 -> error ~2^-12 random.
// ---------------------------------------------------------------------------
#define BATCH 4
#define SEQ   2048
#define CH    1024
#define MTOT  (BATCH * SEQ)

typedef __half h16;
typedef __half2 h162;

__device__ h16 g_xh[MTOT * CH], g_xl[MTOT * CH];
__device__ h16 g_Wqh[CH * CH], g_Wkh[CH * CH], g_Wvh[CH * CH], g_Woh[CH * CH];
__device__ h16 g_Qh[MTOT * CH], g_Ql[MTOT * CH];
__device__ h16 g_Kh[MTOT * CH];
__device__ h16 g_Vh[MTOT * CH];
__device__ h16 g_Oh[MTOT * CH], g_Ol[MTOT * CH];
__device__ float g_S[BATCH * SEQ * SEQ];
__device__ h16 g_Ph[BATCH * SEQ * SEQ], g_Pl[BATCH * SEQ * SEQ];

#define TILE_M 128
#define TILE_N 128
#define BK     32
#define NTHREADS 256

// smem per stage: A hi + A lo (128r x 32k, stride 80B) + B hi only.
#define AROW  80
#define AMAT  10240
#define OFF_AH 0
#define OFF_AL AMAT
#define OFF_BH (2 * AMAT)
#define STAGE  30720
#define NSTAGE 3
#define SMEM_TOTAL (NSTAGE * STAGE)   // 92160

__device__ __forceinline__ uint32_t smem_u32(const void* p) {
    uint32_t a;
    asm("{ .reg .u64 t; cvta.to.shared.u64 t, %1; cvt.u32.u64 %0, t; }" : "=r"(a) : "l"(p));
    return a;
}
#define CP16(dst, src) asm volatile("cp.async.cg.shared.global [%0], [%1], 16;" :: "r"(dst), "l"(src))
#define CP_COMMIT()    asm volatile("cp.async.commit_group;" ::: "memory")
#define CP_WAIT1()     asm volatile("cp.async.wait_group 1;" ::: "memory")

__device__ __forceinline__ void ldsm4(uint32_t* r, uint32_t addr) {
    asm volatile("ldmatrix.sync.aligned.m8n8.x4.shared.b16 {%0,%1,%2,%3}, [%4];"
                 : "=r"(r[0]), "=r"(r[1]), "=r"(r[2]), "=r"(r[3]) : "r"(addr));
}
__device__ __forceinline__ void ldsm4t(uint32_t* r, uint32_t addr) {
    asm volatile("ldmatrix.sync.aligned.m8n8.x4.trans.shared.b16 {%0,%1,%2,%3}, [%4];"
                 : "=r"(r[0]), "=r"(r[1]), "=r"(r[2]), "=r"(r[3]) : "r"(addr));
}
__device__ __forceinline__ void mma16816(float* d, const uint32_t* a, uint32_t b0, uint32_t b1) {
    asm volatile(
        "mma.sync.aligned.m16n8k16.row.col.f32.f16.f16.f32 "
        "{%0,%1,%2,%3},{%4,%5,%6,%7},{%8,%9},{%0,%1,%2,%3};"
        : "+f"(d[0]), "+f"(d[1]), "+f"(d[2]), "+f"(d[3])
        : "r"(a[0]), "r"(a[1]), "r"(a[2]), "r"(a[3]), "r"(b0), "r"(b1));
}
__device__ __forceinline__ void cvt_split(float x, h16& h, h16& l) {
    h = __float2half_rn(x);
    l = __float2half_rn(x - __half2float(h));
}

// ---------------------------------------------------------------------------
__global__ void split_pair(const float* __restrict__ s, h16* __restrict__ h,
                           h16* __restrict__ l, int n)
{
    const int i = 4 * (blockIdx.x * blockDim.x + threadIdx.x);
    if (i >= n) return;
    float4 v = *reinterpret_cast<const float4*>(s + i);
    h16 h0, l0, h1, l1, h2, l2, h3, l3;
    cvt_split(v.x, h0, l0); cvt_split(v.y, h1, l1);
    cvt_split(v.z, h2, l2); cvt_split(v.w, h3, l3);
    *reinterpret_cast<h162*>(h + i)     = {h0, h1};
    *reinterpret_cast<h162*>(h + i + 2) = {h2, h3};
    *reinterpret_cast<h162*>(l + i)     = {l0, l1};
    *reinterpret_cast<h162*>(l + i + 2) = {l2, l3};
}
__global__ void split_single(const float* __restrict__ s, h16* __restrict__ h, int n)
{
    const int i = 4 * (blockIdx.x * blockDim.x + threadIdx.x);
    if (i >= n) return;
    float4 v = *reinterpret_cast<const float4*>(s + i);
    *reinterpret_cast<h162*>(h + i)     = {__float2half_rn(v.x), __float2half_rn(v.y)};
    *reinterpret_cast<h162*>(h + i + 2) = {__float2half_rn(v.z), __float2half_rn(v.w)};
}

// ---------------------------------------------------------------------------
// C = alpha * (Ah+Al) @ op(Bh) (+bias) (+RoPE)
//  BN=false: B [N,K] k-major (non-trans ldmatrix).
//  BN=true : B [K,N] n-major (ldmatrix.trans).
//  EPI: 0 = fp32 out, 1 = fp16 hi+lo out, 2 = fp16 hi-only out.
// ---------------------------------------------------------------------------
template<bool BN, bool ROPE, bool CSKIP, bool CKLIM, int EPI>
__global__ __launch_bounds__(NTHREADS, 1)
void gemm_h2(const h16* __restrict__ Ah, const h16* __restrict__ Al,
             const h16* __restrict__ Bh,
             const float* __restrict__ bias,
             float* __restrict__ Cf, h16* __restrict__ Ch, h16* __restrict__ Cl,
             int M, int N, int K,
             long long sA, long long sB, long long sC, float alpha)
{
    constexpr int BROW = BN ? 272 : 80;
    constexpr int BMAT = BN ? 8704 : 10240;   // 32*272 or 128*80
    (void)BMAT;

    extern __shared__ __align__(256) char smem[];
    const uint32_t sbase = smem_u32(smem);

    const int m0 = blockIdx.y * TILE_M;
    const int n0 = blockIdx.x * TILE_N;
    if (CSKIP && n0 >= m0 + TILE_M) return;

    const h16* Ahb = Ah + (long long)blockIdx.z * sA;
    const h16* Alb = Al + (long long)blockIdx.z * sA;
    const h16* Bhb = Bh + (long long)blockIdx.z * sB;

    const int tid = threadIdx.x;
    const int wid = tid >> 5;
    const int lid = tid & 31;
    const int warp_m = wid >> 2;      // 0..1 -> 64-row slab
    const int warp_n = wid & 3;       // 0..3 -> 32-col slab

    const int Kend  = CKLIM ? (m0 + TILE_M) : K;
    const int NITER = Kend / BK;

    float acc[4][4][4];
    #pragma unroll
    for (int i = 0; i < 4; i++)
        #pragma unroll
        for (int j = 0; j < 4; j++)
            #pragma unroll
            for (int k = 0; k < 4; k++) acc[i][j][k] = 0.f;

    auto issue = [&](int it) {
        if (it < NITER) {
            const uint32_t sb = sbase + (it % NSTAGE) * STAGE;
            const int kc = it * BK;
            #pragma unroll
            for (int i = 0; i < 2; ++i) {                 // A: 512 16B chunks
                const int c  = tid + i * NTHREADS;
                const int r  = c >> 2;
                const int ch = c & 3;
                const size_t g = (size_t)(m0 + r) * K + kc + ch * 8;
                const uint32_t so = (uint32_t)(r * AROW + ch * 16);
                CP16(sb + OFF_AH + so, Ahb + g);
                CP16(sb + OFF_AL + so, Alb + g);
            }
            if (!BN) {
                #pragma unroll
                for (int i = 0; i < 2; ++i) {             // B k-major, hi only
                    const int c  = tid + i * NTHREADS;
                    const int r  = c >> 2;
                    const int ch = c & 3;
                    const size_t g = (size_t)(n0 + r) * K + kc + ch * 8;
                    const uint32_t so = (uint32_t)(r * BROW + ch * 16);
                    CP16(sb + OFF_BH + so, Bhb + g);
                }
            } else {
                #pragma unroll
                for (int i = 0; i < 2; ++i) {             // B n-major: 32k x 128n
                    const int c  = tid + i * NTHREADS;
                    const int kr = c >> 4;
                    const int ch = c & 15;
                    const size_t g = (size_t)(kc + kr) * N + n0 + ch * 8;
                    const uint32_t so = (uint32_t)(kr * BROW + ch * 16);
                    CP16(sb + OFF_BH + so, Bhb + g);
                }
            }
        }
        CP_COMMIT();
    };

    const int a_r = (lid & 15);
    const int a_c = (lid >> 4) << 3;
    const int b_r = (lid & 7) + ((lid >> 4) << 3);
    const int b_c = ((lid >> 3) & 1) << 3;
    const int t_k = (lid & 7) + (((lid >> 3) & 1) << 3);
    const int t_n = (lid >> 4) << 3;

    issue(0);
    issue(1);

    for (int it = 0; it < NITER; ++it) {
        CP_WAIT1();
        __syncthreads();
        const uint32_t sstage = sbase + (it % NSTAGE) * STAGE;

        #pragma unroll
        for (int kk = 0; kk < BK; kk += 16) {
            uint32_t ah[16], al[16], bh[8];
            #pragma unroll
            for (int mt = 0; mt < 4; ++mt) {
                const uint32_t addr = sstage + OFF_AH +
                    (uint32_t)((warp_m * 64 + mt * 16 + a_r) * AROW + (kk + a_c) * 2);
                ldsm4(ah + mt * 4, addr);
                ldsm4(al + mt * 4, addr + AMAT);
            }
            if (!BN) {
                #pragma unroll
                for (int nt = 0; nt < 2; ++nt) {
                    const uint32_t addr = sstage + OFF_BH +
                        (uint32_t)((warp_n * 32 + nt * 16 + b_r) * BROW + (kk + b_c) * 2);
                    ldsm4(bh + nt * 4, addr);
                }
            } else {
                #pragma unroll
                for (int p = 0; p < 2; ++p) {
                    const uint32_t addr = sstage + OFF_BH +
                        (uint32_t)((kk + t_k) * BROW + (warp_n * 32 + p * 16 + t_n) * 2);
                    ldsm4t(bh + p * 4, addr);
                }
            }
            #pragma unroll
            for (int mt = 0; mt < 4; ++mt)
                #pragma unroll
                for (int nt = 0; nt < 4; ++nt) {
                    const uint32_t* bhp = &bh[(nt >> 1) * 4 + (nt & 1) * 2];
                    mma16816(acc[mt][nt], ah + mt * 4, bhp[0], bhp[1]);  // hi*hi
                    mma16816(acc[mt][nt], al + mt * 4, bhp[0], bhp[1]);  // lo*hi
                }
        }
        issue(it + 2);
    }

    // ---- epilogue ----
    const int mbase = m0 + warp_m * 64 + (lid >> 2);
    const int nbase = n0 + warp_n * 32 + (lid & 3) * 2;

    float binv[4];
    #pragma unroll
    for (int nt = 0; nt < 4; ++nt)
        if (ROPE) binv[nt] = powf(10000.0f, -(float)(nbase + nt * 8) / (float)N);

    #pragma unroll
    for (int mt = 0; mt < 4; ++mt) {
        #pragma unroll
        for (int h = 0; h < 2; ++h) {
            const int m = mbase + mt * 16 + h * 8;
            const int t = m & (SEQ - 1);
            #pragma unroll
            for (int nt = 0; nt < 4; ++nt) {
                const int n = nbase + nt * 8;
                float v0 = acc[mt][nt][h * 2 + 0] * alpha;
                float v1 = acc[mt][nt][h * 2 + 1] * alpha;
                if (bias) { v0 += bias[n]; v1 += bias[n + 1]; }
                if (ROPE) {
                    float s, co;
                    sincosf((float)t * binv[nt], &s, &co);
                    const float x0 = v0, x1 = v1;
                    v0 = x0 * co - x1 * s;
                    v1 = x1 * co + x0 * s;
                }
                const size_t off = (size_t)m * N + n + (size_t)blockIdx.z * sC;
                if (EPI == 1) {
                    h16 h0, l0, h1, l1;
                    cvt_split(v0, h0, l0); cvt_split(v1, h1, l1);
                    *reinterpret_cast<h162*>(Ch + off) = {h0, h1};
                    *reinterpret_cast<h162*>(Cl + off) = {l0, l1};
                } else if (EPI == 2) {
                    *reinterpret_cast<h162*>(Ch + off) =
                        {__float2half_rn(v0), __float2half_rn(v1)};
                } else {
                    *reinterpret_cast<float2*>(Cf + off) = make_float2(v0, v1);
                }
            }
        }
    }
}

// ---------------------------------------------------------------------------
// Causal softmax: fp32 S row -> hi/lo fp16 P row; zero-fills to 128 boundary.
// ---------------------------------------------------------------------------
__global__ __launch_bounds__(256)
void softmax_split(float* __restrict__ S, h16* __restrict__ Ph,
                   h16* __restrict__ Pl, int T)
{
    const long long row = blockIdx.x;
    const int t = (int)(row % T);
    float* s = S + row * (long long)T;
    h16* ph = Ph + row * (long long)T;
    h16* pl = Pl + row * (long long)T;
    const int len  = t + 1;
    const int zlim = ((t >> 7) + 1) << 7;
    const int tid = threadIdx.x;

    __shared__ float sh[8];
    __shared__ float bcast;

    float mx = -3.0e38f;
    for (int i = tid; i < len; i += 256) mx = fmaxf(mx, s[i]);
    #pragma unroll
    for (int o = 16; o > 0; o >>= 1) mx = fmaxf(mx, __shfl_xor_sync(0xffffffffu, mx, o));
    if ((tid & 31) == 0) sh[tid >> 5] = mx;
    __syncthreads();
    if (tid == 0) {
        float m = sh[0];
        #pragma unroll
        for (int i = 1; i < 8; i++) m = fmaxf(m, sh[i]);
        bcast = m;
    }
    __syncthreads();
    mx = bcast;

    float sum = 0.f;
    for (int i = tid; i < len; i += 256) {
        float e = expf(s[i] - mx);
        s[i] = e;
        sum += e;
    }
    #pragma unroll
    for (int o = 16; o > 0; o >>= 1) sum += __shfl_xor_sync(0xffffffffu, sum, o);
    __syncthreads();
    if ((tid & 31) == 0) sh[tid >> 5] = sum;
    __syncthreads();
    if (tid == 0) {
        float acc = 0.f;
        #pragma unroll
        for (int i = 0; i < 8; i++) acc += sh[i];
        bcast = acc;
    }
    __syncthreads();
    const float invs = 1.0f / bcast;

    for (int i = tid; i < len; i += 256) {
        h16 h, l;
        cvt_split(s[i] * invs, h, l);
        ph[i] = h; pl[i] = l;
    }
    const h16 z = __float2half_rn(0.f);
    for (int i = len + tid; i < zlim; i += 256) { ph[i] = z; pl[i] = z; }
}

// ---------------------------------------------------------------------------
// kernel_launch: x, Wq, bq, Wk, bk, Wv, bv, Wo, bo
// ---------------------------------------------------------------------------
extern "C" void kernel_launch(void* const* d_in, const int* in_sizes, int n_in,
                              void* d_out, int out_size)
{
    const float* x  = (const float*)d_in[0];
    const float* Wq = (const float*)d_in[1];
    const float* bq = (const float*)d_in[2];
    const float* Wk = (const float*)d_in[3];
    const float* bk = (const float*)d_in[4];
    const float* Wv = (const float*)d_in[5];
    const float* bv = (const float*)d_in[6];
    const float* Wo = (const float*)d_in[7];
    const float* bo = (const float*)d_in[8];
    float* out = (float*)d_out;

    h16 *xh, *xl, *Wqh, *Wkh, *Wvh, *Woh;
    h16 *Qh, *Ql, *Kh, *Vh, *Oh, *Ol, *Ph, *Pl;
    float* pS;
    cudaGetSymbolAddress((void**)&xh, g_xh);   cudaGetSymbolAddress((void**)&xl, g_xl);
    cudaGetSymbolAddress((void**)&Wqh, g_Wqh); cudaGetSymbolAddress((void**)&Wkh, g_Wkh);
    cudaGetSymbolAddress((void**)&Wvh, g_Wvh); cudaGetSymbolAddress((void**)&Woh, g_Woh);
    cudaGetSymbolAddress((void**)&Qh, g_Qh);   cudaGetSymbolAddress((void**)&Ql, g_Ql);
    cudaGetSymbolAddress((void**)&Kh, g_Kh);
    cudaGetSymbolAddress((void**)&Vh, g_Vh);
    cudaGetSymbolAddress((void**)&Oh, g_Oh);   cudaGetSymbolAddress((void**)&Ol, g_Ol);
    cudaGetSymbolAddress((void**)&Ph, g_Ph);   cudaGetSymbolAddress((void**)&Pl, g_Pl);
    cudaGetSymbolAddress((void**)&pS, g_S);

    const int B = BATCH, T = SEQ, C = CH, M = MTOT;
    const long long sTC = (long long)T * C;
    const long long sTT = (long long)T * T;

    cudaFuncSetAttribute(gemm_h2<true,  true,  false, false, 1>, cudaFuncAttributeMaxDynamicSharedMemorySize, SMEM_TOTAL);
    cudaFuncSetAttribute(gemm_h2<true,  true,  false, false, 2>, cudaFuncAttributeMaxDynamicSharedMemorySize, SMEM_TOTAL);
    cudaFuncSetAttribute(gemm_h2<true,  false, false, false, 2>, cudaFuncAttributeMaxDynamicSharedMemorySize, SMEM_TOTAL);
    cudaFuncSetAttribute(gemm_h2<false, false, true,  false, 0>, cudaFuncAttributeMaxDynamicSharedMemorySize, SMEM_TOTAL);
    cudaFuncSetAttribute(gemm_h2<true,  false, false, true,  1>, cudaFuncAttributeMaxDynamicSharedMemorySize, SMEM_TOTAL);
    cudaFuncSetAttribute(gemm_h2<true,  false, false, false, 0>, cudaFuncAttributeMaxDynamicSharedMemorySize, SMEM_TOTAL);

    split_pair<<<(M * C / 4 + 255) / 256, 256>>>(x, xh, xl, M * C);
    split_single<<<(C * C / 4 + 255) / 256, 256>>>(Wq, Wqh, C * C);
    split_single<<<(C * C / 4 + 255) / 256, 256>>>(Wk, Wkh, C * C);
    split_single<<<(C * C / 4 + 255) / 256, 256>>>(Wv, Wvh, C * C);
    split_single<<<(C * C / 4 + 255) / 256, 256>>>(Wo, Woh, C * C);

    dim3 blk(NTHREADS);
    dim3 gridProj(C / TILE_N, M / TILE_M, 1);
    dim3 gridS(T / TILE_N, T / TILE_M, B);
    dim3 gridPV(C / TILE_N, T / TILE_M, B);

    // Q = rope(x Wq + bq) -> fp16 hi/lo; K = rope(x Wk + bk) -> fp16 hi;
    // V = x Wv + bv -> fp16 hi
    gemm_h2<true, true,  false, false, 1><<<gridProj, blk, SMEM_TOTAL>>>(
        xh, xl, Wqh, bq, nullptr, Qh, Ql, M, C, C, 0, 0, 0, 1.0f);
    gemm_h2<true, true,  false, false, 2><<<gridProj, blk, SMEM_TOTAL>>>(
        xh, xl, Wkh, bk, nullptr, Kh, nullptr, M, C, C, 0, 0, 0, 1.0f);
    gemm_h2<true, false, false, false, 2><<<gridProj, blk, SMEM_TOTAL>>>(
        xh, xl, Wvh, bv, nullptr, Vh, nullptr, M, C, C, 0, 0, 0, 1.0f);

    // S = Q K^T / 32 (fp32, causal block skip)
    gemm_h2<false, false, true, false, 0><<<gridS, blk, SMEM_TOTAL>>>(
        Qh, Ql, Kh, nullptr, pS, nullptr, nullptr, T, T, C, sTC, sTC, sTT, 0.03125f);

    softmax_split<<<B * T, 256>>>(pS, Ph, Pl, T);

    // O = P V (K truncated at causal boundary) -> fp16 hi/lo
    gemm_h2<true, false, false, true, 1><<<gridPV, blk, SMEM_TOTAL>>>(
        Ph, Pl, Vh, nullptr, nullptr, Oh, Ol, T, C, T, sTT, sTC, sTC, 1.0f);

    // out = O Wo + bo (fp32)
    gemm_h2<true, false, false, false, 0><<<gridProj, blk, SMEM_TOTAL>>>(
        Oh, Ol, Woh, bo, out, nullptr, nullptr, M, C, C, 0, 0, 0, 1.0f);
}

// round 13
// speedup vs baseline: 1.5013x; 1.1073x over previous
#include <cuda_runtime.h>
#include <cuda_fp16.h>
#include <math.h>
#include <stdint.h>

// ---------------------------------------------------------------------------
// B=4, T=2048, C=1024.  out = softmax(causal(QK^T/32)) V Wo + bo
// mma.sync fp16, fp32 accum. Softmax-sensitive path (Q,K,scores,PV) uses
// A split fp16 hi+lo (2 MMAs/k16); linear value path (V proj, Wo proj)
// uses A hi only (1 MMA/k16). B side always single fp16.
// ---------------------------------------------------------------------------
#define BATCH 4
#define SEQ   2048
#define CH    1024
#define MTOT  (BATCH * SEQ)

typedef __half h16;
typedef __half2 h162;

__device__ h16 g_xh[MTOT * CH], g_xl[MTOT * CH];
__device__ h16 g_Wqh[CH * CH], g_Wkh[CH * CH], g_Wvh[CH * CH], g_Woh[CH * CH];
__device__ h16 g_Qh[MTOT * CH], g_Ql[MTOT * CH];
__device__ h16 g_Kh[MTOT * CH];
__device__ h16 g_Vh[MTOT * CH];
__device__ h16 g_Oh[MTOT * CH];
__device__ float g_S[BATCH * SEQ * SEQ];
__device__ h16 g_Ph[BATCH * SEQ * SEQ], g_Pl[BATCH * SEQ * SEQ];

#define TILE_M 128
#define TILE_N 128
#define BK     32
#define NTHREADS 256

// smem per stage: A hi (+ optional A lo) (128r x 32k, stride 80B) + B hi.
#define AROW  80
#define AMAT  10240
#define OFF_AH 0
#define OFF_AL AMAT
#define OFF_BH (2 * AMAT)
#define STAGE  30720
#define NSTAGE 3
#define SMEM_TOTAL (NSTAGE * STAGE)   // 92160

__device__ __forceinline__ uint32_t smem_u32(const void* p) {
    uint32_t a;
    asm("{ .reg .u64 t; cvta.to.shared.u64 t, %1; cvt.u32.u64 %0, t; }" : "=r"(a) : "l"(p));
    return a;
}
#define CP16(dst, src) asm volatile("cp.async.cg.shared.global [%0], [%1], 16;" :: "r"(dst), "l"(src))
#define CP_COMMIT()    asm volatile("cp.async.commit_group;" ::: "memory")
#define CP_WAIT1()     asm volatile("cp.async.wait_group 1;" ::: "memory")

__device__ __forceinline__ void ldsm4(uint32_t* r, uint32_t addr) {
    asm volatile("ldmatrix.sync.aligned.m8n8.x4.shared.b16 {%0,%1,%2,%3}, [%4];"
                 : "=r"(r[0]), "=r"(r[1]), "=r"(r[2]), "=r"(r[3]) : "r"(addr));
}
__device__ __forceinline__ void ldsm4t(uint32_t* r, uint32_t addr) {
    asm volatile("ldmatrix.sync.aligned.m8n8.x4.trans.shared.b16 {%0,%1,%2,%3}, [%4];"
                 : "=r"(r[0]), "=r"(r[1]), "=r"(r[2]), "=r"(r[3]) : "r"(addr));
}
__device__ __forceinline__ void mma16816(float* d, const uint32_t* a, uint32_t b0, uint32_t b1) {
    asm volatile(
        "mma.sync.aligned.m16n8k16.row.col.f32.f16.f16.f32 "
        "{%0,%1,%2,%3},{%4,%5,%6,%7},{%8,%9},{%0,%1,%2,%3};"
        : "+f"(d[0]), "+f"(d[1]), "+f"(d[2]), "+f"(d[3])
        : "r"(a[0]), "r"(a[1]), "r"(a[2]), "r"(a[3]), "r"(b0), "r"(b1));
}
__device__ __forceinline__ void cvt_split(float x, h16& h, h16& l) {
    h = __float2half_rn(x);
    l = __float2half_rn(x - __half2float(h));
}

// ---------------------------------------------------------------------------
__global__ void split_pair(const float* __restrict__ s, h16* __restrict__ h,
                           h16* __restrict__ l, int n)
{
    const int i = 4 * (blockIdx.x * blockDim.x + threadIdx.x);
    if (i >= n) return;
    float4 v = *reinterpret_cast<const float4*>(s + i);
    h16 h0, l0, h1, l1, h2, l2, h3, l3;
    cvt_split(v.x, h0, l0); cvt_split(v.y, h1, l1);
    cvt_split(v.z, h2, l2); cvt_split(v.w, h3, l3);
    *reinterpret_cast<h162*>(h + i)     = {h0, h1};
    *reinterpret_cast<h162*>(h + i + 2) = {h2, h3};
    *reinterpret_cast<h162*>(l + i)     = {l0, l1};
    *reinterpret_cast<h162*>(l + i + 2) = {l2, l3};
}
__global__ void split_single(const float* __restrict__ s, h16* __restrict__ h, int n)
{
    const int i = 4 * (blockIdx.x * blockDim.x + threadIdx.x);
    if (i >= n) return;
    float4 v = *reinterpret_cast<const float4*>(s + i);
    *reinterpret_cast<h162*>(h + i)     = {__float2half_rn(v.x), __float2half_rn(v.y)};
    *reinterpret_cast<h162*>(h + i + 2) = {__float2half_rn(v.z), __float2half_rn(v.w)};
}

// ---------------------------------------------------------------------------
// C = alpha * A @ op(Bh) (+bias) (+RoPE)
//  BN=false: B [N,K] k-major (non-trans ldmatrix).
//  BN=true : B [K,N] n-major (ldmatrix.trans).
//  EPI: 0 = fp32 out, 1 = fp16 hi+lo out, 2 = fp16 hi-only out.
//  AMMA: 2 = A hi+lo (2 MMAs/k16), 1 = A hi only (1 MMA/k16).
// ---------------------------------------------------------------------------
template<bool BN, bool ROPE, bool CSKIP, bool CKLIM, int EPI, int AMMA>
__global__ __launch_bounds__(NTHREADS, 1)
void gemm_h2(const h16* __restrict__ Ah, const h16* __restrict__ Al,
             const h16* __restrict__ Bh,
             const float* __restrict__ bias,
             float* __restrict__ Cf, h16* __restrict__ Ch, h16* __restrict__ Cl,
             int M, int N, int K,
             long long sA, long long sB, long long sC, float alpha)
{
    constexpr int BROW = BN ? 272 : 80;

    extern __shared__ __align__(256) char smem[];
    const uint32_t sbase = smem_u32(smem);

    const int m0 = blockIdx.y * TILE_M;
    const int n0 = blockIdx.x * TILE_N;
    if (CSKIP && n0 >= m0 + TILE_M) return;

    const h16* Ahb = Ah + (long long)blockIdx.z * sA;
    const h16* Alb = (AMMA == 2) ? Al + (long long)blockIdx.z * sA : nullptr;
    const h16* Bhb = Bh + (long long)blockIdx.z * sB;

    const int tid = threadIdx.x;
    const int wid = tid >> 5;
    const int lid = tid & 31;
    const int warp_m = wid >> 2;      // 0..1 -> 64-row slab
    const int warp_n = wid & 3;       // 0..3 -> 32-col slab

    const int Kend  = CKLIM ? (m0 + TILE_M) : K;
    const int NITER = Kend / BK;

    float acc[4][4][4];
    #pragma unroll
    for (int i = 0; i < 4; i++)
        #pragma unroll
        for (int j = 0; j < 4; j++)
            #pragma unroll
            for (int k = 0; k < 4; k++) acc[i][j][k] = 0.f;

    auto issue = [&](int it) {
        if (it < NITER) {
            const uint32_t sb = sbase + (it % NSTAGE) * STAGE;
            const int kc = it * BK;
            #pragma unroll
            for (int i = 0; i < 2; ++i) {                 // A: 512 16B chunks
                const int c  = tid + i * NTHREADS;
                const int r  = c >> 2;
                const int ch = c & 3;
                const size_t g = (size_t)(m0 + r) * K + kc + ch * 8;
                const uint32_t so = (uint32_t)(r * AROW + ch * 16);
                CP16(sb + OFF_AH + so, Ahb + g);
                if (AMMA == 2) CP16(sb + OFF_AL + so, Alb + g);
            }
            if (!BN) {
                #pragma unroll
                for (int i = 0; i < 2; ++i) {             // B k-major
                    const int c  = tid + i * NTHREADS;
                    const int r  = c >> 2;
                    const int ch = c & 3;
                    const size_t g = (size_t)(n0 + r) * K + kc + ch * 8;
                    const uint32_t so = (uint32_t)(r * BROW + ch * 16);
                    CP16(sb + OFF_BH + so, Bhb + g);
                }
            } else {
                #pragma unroll
                for (int i = 0; i < 2; ++i) {             // B n-major: 32k x 128n
                    const int c  = tid + i * NTHREADS;
                    const int kr = c >> 4;
                    const int ch = c & 15;
                    const size_t g = (size_t)(kc + kr) * N + n0 + ch * 8;
                    const uint32_t so = (uint32_t)(kr * BROW + ch * 16);
                    CP16(sb + OFF_BH + so, Bhb + g);
                }
            }
        }
        CP_COMMIT();
    };

    const int a_r = (lid & 15);
    const int a_c = (lid >> 4) << 3;
    const int b_r = (lid & 7) + ((lid >> 4) << 3);
    const int b_c = ((lid >> 3) & 1) << 3;
    const int t_k = (lid & 7) + (((lid >> 3) & 1) << 3);
    const int t_n = (lid >> 4) << 3;

    issue(0);
    issue(1);

    for (int it = 0; it < NITER; ++it) {
        CP_WAIT1();
        __syncthreads();
        const uint32_t sstage = sbase + (it % NSTAGE) * STAGE;

        #pragma unroll
        for (int kk = 0; kk < BK; kk += 16) {
            uint32_t ah[16], al[16], bh[8];
            #pragma unroll
            for (int mt = 0; mt < 4; ++mt) {
                const uint32_t addr = sstage + OFF_AH +
                    (uint32_t)((warp_m * 64 + mt * 16 + a_r) * AROW + (kk + a_c) * 2);
                ldsm4(ah + mt * 4, addr);
                if (AMMA == 2) ldsm4(al + mt * 4, addr + AMAT);
            }
            if (!BN) {
                #pragma unroll
                for (int nt = 0; nt < 2; ++nt) {
                    const uint32_t addr = sstage + OFF_BH +
                        (uint32_t)((warp_n * 32 + nt * 16 + b_r) * BROW + (kk + b_c) * 2);
                    ldsm4(bh + nt * 4, addr);
                }
            } else {
                #pragma unroll
                for (int p = 0; p < 2; ++p) {
                    const uint32_t addr = sstage + OFF_BH +
                        (uint32_t)((kk + t_k) * BROW + (warp_n * 32 + p * 16 + t_n) * 2);
                    ldsm4t(bh + p * 4, addr);
                }
            }
            #pragma unroll
            for (int mt = 0; mt < 4; ++mt)
                #pragma unroll
                for (int nt = 0; nt < 4; ++nt) {
                    const uint32_t* bhp = &bh[(nt >> 1) * 4 + (nt & 1) * 2];
                    mma16816(acc[mt][nt], ah + mt * 4, bhp[0], bhp[1]);   // hi
                    if (AMMA == 2)
                        mma16816(acc[mt][nt], al + mt * 4, bhp[0], bhp[1]); // lo
                }
        }
        issue(it + 2);
    }

    // ---- epilogue ----
    const int mbase = m0 + warp_m * 64 + (lid >> 2);
    const int nbase = n0 + warp_n * 32 + (lid & 3) * 2;

    float binv[4];
    #pragma unroll
    for (int nt = 0; nt < 4; ++nt)
        if (ROPE) binv[nt] = powf(10000.0f, -(float)(nbase + nt * 8) / (float)N);

    #pragma unroll
    for (int mt = 0; mt < 4; ++mt) {
        #pragma unroll
        for (int h = 0; h < 2; ++h) {
            const int m = mbase + mt * 16 + h * 8;
            const int t = m & (SEQ - 1);
            #pragma unroll
            for (int nt = 0; nt < 4; ++nt) {
                const int n = nbase + nt * 8;
                float v0 = acc[mt][nt][h * 2 + 0] * alpha;
                float v1 = acc[mt][nt][h * 2 + 1] * alpha;
                if (bias) { v0 += bias[n]; v1 += bias[n + 1]; }
                if (ROPE) {
                    float s, co;
                    sincosf((float)t * binv[nt], &s, &co);
                    const float x0 = v0, x1 = v1;
                    v0 = x0 * co - x1 * s;
                    v1 = x1 * co + x0 * s;
                }
                const size_t off = (size_t)m * N + n + (size_t)blockIdx.z * sC;
                if (EPI == 1) {
                    h16 h0, l0, h1, l1;
                    cvt_split(v0, h0, l0); cvt_split(v1, h1, l1);
                    *reinterpret_cast<h162*>(Ch + off) = {h0, h1};
                    *reinterpret_cast<h162*>(Cl + off) = {l0, l1};
                } else if (EPI == 2) {
                    *reinterpret_cast<h162*>(Ch + off) =
                        {__float2half_rn(v0), __float2half_rn(v1)};
                } else {
                    *reinterpret_cast<float2*>(Cf + off) = make_float2(v0, v1);
                }
            }
        }
    }
}

// ---------------------------------------------------------------------------
// Causal softmax: fp32 S row -> hi/lo fp16 P row; zero-fills to 128 boundary.
// ---------------------------------------------------------------------------
__global__ __launch_bounds__(256)
void softmax_split(float* __restrict__ S, h16* __restrict__ Ph,
                   h16* __restrict__ Pl, int T)
{
    const long long row = blockIdx.x;
    const int t = (int)(row % T);
    float* s = S + row * (long long)T;
    h16* ph = Ph + row * (long long)T;
    h16* pl = Pl + row * (long long)T;
    const int len  = t + 1;
    const int zlim = ((t >> 7) + 1) << 7;
    const int tid = threadIdx.x;

    __shared__ float sh[8];
    __shared__ float bcast;

    float mx = -3.0e38f;
    for (int i = tid; i < len; i += 256) mx = fmaxf(mx, s[i]);
    #pragma unroll
    for (int o = 16; o > 0; o >>= 1) mx = fmaxf(mx, __shfl_xor_sync(0xffffffffu, mx, o));
    if ((tid & 31) == 0) sh[tid >> 5] = mx;
    __syncthreads();
    if (tid == 0) {
        float m = sh[0];
        #pragma unroll
        for (int i = 1; i < 8; i++) m = fmaxf(m, sh[i]);
        bcast = m;
    }
    __syncthreads();
    mx = bcast;

    float sum = 0.f;
    for (int i = tid; i < len; i += 256) {
        float e = expf(s[i] - mx);
        s[i] = e;
        sum += e;
    }
    #pragma unroll
    for (int o = 16; o > 0; o >>= 1) sum += __shfl_xor_sync(0xffffffffu, sum, o);
    __syncthreads();
    if ((tid & 31) == 0) sh[tid >> 5] = sum;
    __syncthreads();
    if (tid == 0) {
        float acc = 0.f;
        #pragma unroll
        for (int i = 0; i < 8; i++) acc += sh[i];
        bcast = acc;
    }
    __syncthreads();
    const float invs = 1.0f / bcast;

    for (int i = tid; i < len; i += 256) {
        h16 h, l;
        cvt_split(s[i] * invs, h, l);
        ph[i] = h; pl[i] = l;
    }
    const h16 z = __float2half_rn(0.f);
    for (int i = len + tid; i < zlim; i += 256) { ph[i] = z; pl[i] = z; }
}

// ---------------------------------------------------------------------------
// kernel_launch: x, Wq, bq, Wk, bk, Wv, bv, Wo, bo
// ---------------------------------------------------------------------------
extern "C" void kernel_launch(void* const* d_in, const int* in_sizes, int n_in,
                              void* d_out, int out_size)
{
    const float* x  = (const float*)d_in[0];
    const float* Wq = (const float*)d_in[1];
    const float* bq = (const float*)d_in[2];
    const float* Wk = (const float*)d_in[3];
    const float* bk = (const float*)d_in[4];
    const float* Wv = (const float*)d_in[5];
    const float* bv = (const float*)d_in[6];
    const float* Wo = (const float*)d_in[7];
    const float* bo = (const float*)d_in[8];
    float* out = (float*)d_out;

    h16 *xh, *xl, *Wqh, *Wkh, *Wvh, *Woh;
    h16 *Qh, *Ql, *Kh, *Vh, *Oh, *Ph, *Pl;
    float* pS;
    cudaGetSymbolAddress((void**)&xh, g_xh);   cudaGetSymbolAddress((void**)&xl, g_xl);
    cudaGetSymbolAddress((void**)&Wqh, g_Wqh); cudaGetSymbolAddress((void**)&Wkh, g_Wkh);
    cudaGetSymbolAddress((void**)&Wvh, g_Wvh); cudaGetSymbolAddress((void**)&Woh, g_Woh);
    cudaGetSymbolAddress((void**)&Qh, g_Qh);   cudaGetSymbolAddress((void**)&Ql, g_Ql);
    cudaGetSymbolAddress((void**)&Kh, g_Kh);
    cudaGetSymbolAddress((void**)&Vh, g_Vh);
    cudaGetSymbolAddress((void**)&Oh, g_Oh);
    cudaGetSymbolAddress((void**)&Ph, g_Ph);   cudaGetSymbolAddress((void**)&Pl, g_Pl);
    cudaGetSymbolAddress((void**)&pS, g_S);

    const int B = BATCH, T = SEQ, C = CH, M = MTOT;
    const long long sTC = (long long)T * C;
    const long long sTT = (long long)T * T;

    cudaFuncSetAttribute(gemm_h2<true,  true,  false, false, 1, 2>, cudaFuncAttributeMaxDynamicSharedMemorySize, SMEM_TOTAL);
    cudaFuncSetAttribute(gemm_h2<true,  true,  false, false, 2, 2>, cudaFuncAttributeMaxDynamicSharedMemorySize, SMEM_TOTAL);
    cudaFuncSetAttribute(gemm_h2<true,  false, false, false, 2, 1>, cudaFuncAttributeMaxDynamicSharedMemorySize, SMEM_TOTAL);
    cudaFuncSetAttribute(gemm_h2<false, false, true,  false, 0, 2>, cudaFuncAttributeMaxDynamicSharedMemorySize, SMEM_TOTAL);
    cudaFuncSetAttribute(gemm_h2<true,  false, false, true,  2, 2>, cudaFuncAttributeMaxDynamicSharedMemorySize, SMEM_TOTAL);
    cudaFuncSetAttribute(gemm_h2<true,  false, false, false, 0, 1>, cudaFuncAttributeMaxDynamicSharedMemorySize, SMEM_TOTAL);

    split_pair<<<(M * C / 4 + 255) / 256, 256>>>(x, xh, xl, M * C);
    split_single<<<(C * C / 4 + 255) / 256, 256>>>(Wq, Wqh, C * C);
    split_single<<<(C * C / 4 + 255) / 256, 256>>>(Wk, Wkh, C * C);
    split_single<<<(C * C / 4 + 255) / 256, 256>>>(Wv, Wvh, C * C);
    split_single<<<(C * C / 4 + 255) / 256, 256>>>(Wo, Woh, C * C);

    dim3 blk(NTHREADS);
    dim3 gridProj(C / TILE_N, M / TILE_M, 1);
    dim3 gridS(T / TILE_N, T / TILE_M, B);
    dim3 gridPV(C / TILE_N, T / TILE_M, B);

    // Q = rope(x Wq + bq): 2-MMA, hi/lo out.  K = rope(x Wk + bk): 2-MMA, hi.
    // V = x Wv + bv: 1-MMA (x hi only), hi out.
    gemm_h2<true, true,  false, false, 1, 2><<<gridProj, blk, SMEM_TOTAL>>>(
        xh, xl, Wqh, bq, nullptr, Qh, Ql, M, C, C, 0, 0, 0, 1.0f);
    gemm_h2<true, true,  false, false, 2, 2><<<gridProj, blk, SMEM_TOTAL>>>(
        xh, xl, Wkh, bk, nullptr, Kh, nullptr, M, C, C, 0, 0, 0, 1.0f);
    gemm_h2<true, false, false, false, 2, 1><<<gridProj, blk, SMEM_TOTAL>>>(
        xh, nullptr, Wvh, bv, nullptr, Vh, nullptr, M, C, C, 0, 0, 0, 1.0f);

    // S = Q K^T / 32: 2-MMA, fp32 out, causal block skip
    gemm_h2<false, false, true, false, 0, 2><<<gridS, blk, SMEM_TOTAL>>>(
        Qh, Ql, Kh, nullptr, pS, nullptr, nullptr, T, T, C, sTC, sTC, sTT, 0.03125f);

    softmax_split<<<B * T, 256>>>(pS, Ph, Pl, T);

    // O = P V: 2-MMA (P hi/lo), hi-only out (Wo is 1-MMA so lo is unused)
    gemm_h2<true, false, false, true, 2, 2><<<gridPV, blk, SMEM_TOTAL>>>(
        Ph, Pl, Vh, nullptr, nullptr, Oh, nullptr, T, C, T, sTT, sTC, sTC, 1.0f);

    // out = O Wo + bo: 1-MMA (O hi only), fp32 out
    gemm_h2<true, false, false, false, 0, 1><<<gridProj, blk, SMEM_TOTAL>>>(
        Oh, nullptr, Woh, bo, out, nullptr, nullptr, M, C, C, 0, 0, 0, 1.0f);
}

// round 14
// speedup vs baseline: 1.9309x; 1.2861x over previous
#include <cuda_runtime.h>
#include <cuda_fp16.h>
#include <math.h>
#include <stdint.h>

// ---------------------------------------------------------------------------
// B=4, T=2048, C=1024.  out = softmax(causal(QK^T/32)) V Wo + bo
// Pure fp16 mma.sync (fp32 accum) on every GEMM. Measured error model:
// each fp16-rounded operand adds ~2e-4 RSS; total forecast ~7e-4 < 1e-3.
// ---------------------------------------------------------------------------
#define BATCH 4
#define SEQ   2048
#define CH    1024
#define MTOT  (BATCH * SEQ)

typedef __half h16;
typedef __half2 h162;

__device__ h16 g_xh[MTOT * CH];
__device__ h16 g_Wqh[CH * CH], g_Wkh[CH * CH], g_Wvh[CH * CH], g_Woh[CH * CH];
__device__ h16 g_Qh[MTOT * CH];
__device__ h16 g_Kh[MTOT * CH];
__device__ h16 g_Vh[MTOT * CH];
__device__ h16 g_Oh[MTOT * CH];
__device__ float g_S[BATCH * SEQ * SEQ];
__device__ h16 g_Ph[BATCH * SEQ * SEQ];

#define TILE_M 128
#define TILE_N 128
#define BK     32
#define NTHREADS 256

// smem per stage: A (128r x 32k fp16, stride 80B) + B (k-major 128x32 @80B
// or n-major 32x128 @272B).
#define AROW  80
#define AMAT  10240
#define OFF_AH 0
#define OFF_BH AMAT
#define STAGE  20480
#define NSTAGE 3
#define SMEM_TOTAL (NSTAGE * STAGE)   // 61440

__device__ __forceinline__ uint32_t smem_u32(const void* p) {
    uint32_t a;
    asm("{ .reg .u64 t; cvta.to.shared.u64 t, %1; cvt.u32.u64 %0, t; }" : "=r"(a) : "l"(p));
    return a;
}
#define CP16(dst, src) asm volatile("cp.async.cg.shared.global [%0], [%1], 16;" :: "r"(dst), "l"(src))
#define CP_COMMIT()    asm volatile("cp.async.commit_group;" ::: "memory")
#define CP_WAIT1()     asm volatile("cp.async.wait_group 1;" ::: "memory")

__device__ __forceinline__ void ldsm4(uint32_t* r, uint32_t addr) {
    asm volatile("ldmatrix.sync.aligned.m8n8.x4.shared.b16 {%0,%1,%2,%3}, [%4];"
                 : "=r"(r[0]), "=r"(r[1]), "=r"(r[2]), "=r"(r[3]) : "r"(addr));
}
__device__ __forceinline__ void ldsm4t(uint32_t* r, uint32_t addr) {
    asm volatile("ldmatrix.sync.aligned.m8n8.x4.trans.shared.b16 {%0,%1,%2,%3}, [%4];"
                 : "=r"(r[0]), "=r"(r[1]), "=r"(r[2]), "=r"(r[3]) : "r"(addr));
}
__device__ __forceinline__ void mma16816(float* d, const uint32_t* a, uint32_t b0, uint32_t b1) {
    asm volatile(
        "mma.sync.aligned.m16n8k16.row.col.f32.f16.f16.f32 "
        "{%0,%1,%2,%3},{%4,%5,%6,%7},{%8,%9},{%0,%1,%2,%3};"
        : "+f"(d[0]), "+f"(d[1]), "+f"(d[2]), "+f"(d[3])
        : "r"(a[0]), "r"(a[1]), "r"(a[2]), "r"(a[3]), "r"(b0), "r"(b1));
}

// ---------------------------------------------------------------------------
__global__ void split_single(const float* __restrict__ s, h16* __restrict__ h, int n)
{
    const int i = 4 * (blockIdx.x * blockDim.x + threadIdx.x);
    if (i >= n) return;
    float4 v = *reinterpret_cast<const float4*>(s + i);
    *reinterpret_cast<h162*>(h + i)     = {__float2half_rn(v.x), __float2half_rn(v.y)};
    *reinterpret_cast<h162*>(h + i + 2) = {__float2half_rn(v.z), __float2half_rn(v.w)};
}

// ---------------------------------------------------------------------------
// C = alpha * A @ op(B) (+bias) (+RoPE), all fp16 operands, fp32 accum.
//  BN=false: B [N,K] k-major (non-trans ldmatrix).
//  BN=true : B [K,N] n-major (ldmatrix.trans).
//  EPI: 0 = fp32 out, 2 = fp16 out.
// ---------------------------------------------------------------------------
template<bool BN, bool ROPE, bool CSKIP, bool CKLIM, int EPI>
__global__ __launch_bounds__(NTHREADS, 1)
void gemm_h1(const h16* __restrict__ Ah, const h16* __restrict__ Bh,
             const float* __restrict__ bias,
             float* __restrict__ Cf, h16* __restrict__ Ch,
             int M, int N, int K,
             long long sA, long long sB, long long sC, float alpha)
{
    constexpr int BROW = BN ? 272 : 80;

    extern __shared__ __align__(256) char smem[];
    const uint32_t sbase = smem_u32(smem);

    const int m0 = blockIdx.y * TILE_M;
    const int n0 = blockIdx.x * TILE_N;
    if (CSKIP && n0 >= m0 + TILE_M) return;

    const h16* Ahb = Ah + (long long)blockIdx.z * sA;
    const h16* Bhb = Bh + (long long)blockIdx.z * sB;

    const int tid = threadIdx.x;
    const int wid = tid >> 5;
    const int lid = tid & 31;
    const int warp_m = wid >> 2;      // 0..1 -> 64-row slab
    const int warp_n = wid & 3;       // 0..3 -> 32-col slab

    const int Kend  = CKLIM ? (m0 + TILE_M) : K;
    const int NITER = Kend / BK;

    float acc[4][4][4];
    #pragma unroll
    for (int i = 0; i < 4; i++)
        #pragma unroll
        for (int j = 0; j < 4; j++)
            #pragma unroll
            for (int k = 0; k < 4; k++) acc[i][j][k] = 0.f;

    auto issue = [&](int it) {
        if (it < NITER) {
            const uint32_t sb = sbase + (it % NSTAGE) * STAGE;
            const int kc = it * BK;
            #pragma unroll
            for (int i = 0; i < 2; ++i) {                 // A: 512 16B chunks
                const int c  = tid + i * NTHREADS;
                const int r  = c >> 2;
                const int ch = c & 3;
                const size_t g = (size_t)(m0 + r) * K + kc + ch * 8;
                const uint32_t so = (uint32_t)(r * AROW + ch * 16);
                CP16(sb + OFF_AH + so, Ahb + g);
            }
            if (!BN) {
                #pragma unroll
                for (int i = 0; i < 2; ++i) {             // B k-major
                    const int c  = tid + i * NTHREADS;
                    const int r  = c >> 2;
                    const int ch = c & 3;
                    const size_t g = (size_t)(n0 + r) * K + kc + ch * 8;
                    const uint32_t so = (uint32_t)(r * BROW + ch * 16);
                    CP16(sb + OFF_BH + so, Bhb + g);
                }
            } else {
                #pragma unroll
                for (int i = 0; i < 2; ++i) {             // B n-major: 32k x 128n
                    const int c  = tid + i * NTHREADS;
                    const int kr = c >> 4;
                    const int ch = c & 15;
                    const size_t g = (size_t)(kc + kr) * N + n0 + ch * 8;
                    const uint32_t so = (uint32_t)(kr * BROW + ch * 16);
                    CP16(sb + OFF_BH + so, Bhb + g);
                }
            }
        }
        CP_COMMIT();
    };

    const int a_r = (lid & 15);
    const int a_c = (lid >> 4) << 3;
    const int b_r = (lid & 7) + ((lid >> 4) << 3);
    const int b_c = ((lid >> 3) & 1) << 3;
    const int t_k = (lid & 7) + (((lid >> 3) & 1) << 3);
    const int t_n = (lid >> 4) << 3;

    issue(0);
    issue(1);

    for (int it = 0; it < NITER; ++it) {
        CP_WAIT1();
        __syncthreads();
        const uint32_t sstage = sbase + (it % NSTAGE) * STAGE;

        #pragma unroll
        for (int kk = 0; kk < BK; kk += 16) {
            uint32_t ah[16], bh[8];
            #pragma unroll
            for (int mt = 0; mt < 4; ++mt) {
                const uint32_t addr = sstage + OFF_AH +
                    (uint32_t)((warp_m * 64 + mt * 16 + a_r) * AROW + (kk + a_c) * 2);
                ldsm4(ah + mt * 4, addr);
            }
            if (!BN) {
                #pragma unroll
                for (int nt = 0; nt < 2; ++nt) {
                    const uint32_t addr = sstage + OFF_BH +
                        (uint32_t)((warp_n * 32 + nt * 16 + b_r) * BROW + (kk + b_c) * 2);
                    ldsm4(bh + nt * 4, addr);
                }
            } else {
                #pragma unroll
                for (int p = 0; p < 2; ++p) {
                    const uint32_t addr = sstage + OFF_BH +
                        (uint32_t)((kk + t_k) * BROW + (warp_n * 32 + p * 16 + t_n) * 2);
                    ldsm4t(bh + p * 4, addr);
                }
            }
            #pragma unroll
            for (int mt = 0; mt < 4; ++mt)
                #pragma unroll
                for (int nt = 0; nt < 4; ++nt) {
                    const uint32_t* bhp = &bh[(nt >> 1) * 4 + (nt & 1) * 2];
                    mma16816(acc[mt][nt], ah + mt * 4, bhp[0], bhp[1]);
                }
        }
        issue(it + 2);
    }

    // ---- epilogue ----
    const int mbase = m0 + warp_m * 64 + (lid >> 2);
    const int nbase = n0 + warp_n * 32 + (lid & 3) * 2;

    float binv[4];
    #pragma unroll
    for (int nt = 0; nt < 4; ++nt)
        if (ROPE) binv[nt] = powf(10000.0f, -(float)(nbase + nt * 8) / (float)N);

    #pragma unroll
    for (int mt = 0; mt < 4; ++mt) {
        #pragma unroll
        for (int h = 0; h < 2; ++h) {
            const int m = mbase + mt * 16 + h * 8;
            const int t = m & (SEQ - 1);
            #pragma unroll
            for (int nt = 0; nt < 4; ++nt) {
                const int n = nbase + nt * 8;
                float v0 = acc[mt][nt][h * 2 + 0] * alpha;
                float v1 = acc[mt][nt][h * 2 + 1] * alpha;
                if (bias) { v0 += bias[n]; v1 += bias[n + 1]; }
                if (ROPE) {
                    float s, co;
                    sincosf((float)t * binv[nt], &s, &co);
                    const float x0 = v0, x1 = v1;
                    v0 = x0 * co - x1 * s;
                    v1 = x1 * co + x0 * s;
                }
                const size_t off = (size_t)m * N + n + (size_t)blockIdx.z * sC;
                if (EPI == 2) {
                    *reinterpret_cast<h162*>(Ch + off) =
                        {__float2half_rn(v0), __float2half_rn(v1)};
                } else {
                    *reinterpret_cast<float2*>(Cf + off) = make_float2(v0, v1);
                }
            }
        }
    }
}

// ---------------------------------------------------------------------------
// Causal softmax: fp32 S row -> fp16 P row; zero-fills to 128 boundary.
// ---------------------------------------------------------------------------
__global__ __launch_bounds__(256)
void softmax_h(float* __restrict__ S, h16* __restrict__ Ph, int T)
{
    const long long row = blockIdx.x;
    const int t = (int)(row % T);
    float* s = S + row * (long long)T;
    h16* ph = Ph + row * (long long)T;
    const int len  = t + 1;
    const int zlim = ((t >> 7) + 1) << 7;
    const int tid = threadIdx.x;

    __shared__ float sh[8];
    __shared__ float bcast;

    float mx = -3.0e38f;
    for (int i = tid; i < len; i += 256) mx = fmaxf(mx, s[i]);
    #pragma unroll
    for (int o = 16; o > 0; o >>= 1) mx = fmaxf(mx, __shfl_xor_sync(0xffffffffu, mx, o));
    if ((tid & 31) == 0) sh[tid >> 5] = mx;
    __syncthreads();
    if (tid == 0) {
        float m = sh[0];
        #pragma unroll
        for (int i = 1; i < 8; i++) m = fmaxf(m, sh[i]);
        bcast = m;
    }
    __syncthreads();
    mx = bcast;

    float sum = 0.f;
    for (int i = tid; i < len; i += 256) {
        float e = expf(s[i] - mx);
        s[i] = e;
        sum += e;
    }
    #pragma unroll
    for (int o = 16; o > 0; o >>= 1) sum += __shfl_xor_sync(0xffffffffu, sum, o);
    __syncthreads();
    if ((tid & 31) == 0) sh[tid >> 5] = sum;
    __syncthreads();
    if (tid == 0) {
        float acc = 0.f;
        #pragma unroll
        for (int i = 0; i < 8; i++) acc += sh[i];
        bcast = acc;
    }
    __syncthreads();
    const float invs = 1.0f / bcast;

    for (int i = tid; i < len; i += 256)
        ph[i] = __float2half_rn(s[i] * invs);
    const h16 z = __float2half_rn(0.f);
    for (int i = len + tid; i < zlim; i += 256) ph[i] = z;
}

// ---------------------------------------------------------------------------
// kernel_launch: x, Wq, bq, Wk, bk, Wv, bv, Wo, bo
// ---------------------------------------------------------------------------
extern "C" void kernel_launch(void* const* d_in, const int* in_sizes, int n_in,
                              void* d_out, int out_size)
{
    const float* x  = (const float*)d_in[0];
    const float* Wq = (const float*)d_in[1];
    const float* bq = (const float*)d_in[2];
    const float* Wk = (const float*)d_in[3];
    const float* bk = (const float*)d_in[4];
    const float* Wv = (const float*)d_in[5];
    const float* bv = (const float*)d_in[6];
    const float* Wo = (const float*)d_in[7];
    const float* bo = (const float*)d_in[8];
    float* out = (float*)d_out;

    h16 *xh, *Wqh, *Wkh, *Wvh, *Woh;
    h16 *Qh, *Kh, *Vh, *Oh, *Ph;
    float* pS;
    cudaGetSymbolAddress((void**)&xh, g_xh);
    cudaGetSymbolAddress((void**)&Wqh, g_Wqh); cudaGetSymbolAddress((void**)&Wkh, g_Wkh);
    cudaGetSymbolAddress((void**)&Wvh, g_Wvh); cudaGetSymbolAddress((void**)&Woh, g_Woh);
    cudaGetSymbolAddress((void**)&Qh, g_Qh);
    cudaGetSymbolAddress((void**)&Kh, g_Kh);
    cudaGetSymbolAddress((void**)&Vh, g_Vh);
    cudaGetSymbolAddress((void**)&Oh, g_Oh);
    cudaGetSymbolAddress((void**)&Ph, g_Ph);
    cudaGetSymbolAddress((void**)&pS, g_S);

    const int B = BATCH, T = SEQ, C = CH, M = MTOT;
    const long long sTC = (long long)T * C;
    const long long sTT = (long long)T * T;

    cudaFuncSetAttribute(gemm_h1<true,  true,  false, false, 2>, cudaFuncAttributeMaxDynamicSharedMemorySize, SMEM_TOTAL);
    cudaFuncSetAttribute(gemm_h1<true,  false, false, false, 2>, cudaFuncAttributeMaxDynamicSharedMemorySize, SMEM_TOTAL);
    cudaFuncSetAttribute(gemm_h1<false, false, true,  false, 0>, cudaFuncAttributeMaxDynamicSharedMemorySize, SMEM_TOTAL);
    cudaFuncSetAttribute(gemm_h1<true,  false, false, true,  2>, cudaFuncAttributeMaxDynamicSharedMemorySize, SMEM_TOTAL);
    cudaFuncSetAttribute(gemm_h1<true,  false, false, false, 0>, cudaFuncAttributeMaxDynamicSharedMemorySize, SMEM_TOTAL);

    split_single<<<(M * C / 4 + 255) / 256, 256>>>(x, xh, M * C);
    split_single<<<(C * C / 4 + 255) / 256, 256>>>(Wq, Wqh, C * C);
    split_single<<<(C * C / 4 + 255) / 256, 256>>>(Wk, Wkh, C * C);
    split_single<<<(C * C / 4 + 255) / 256, 256>>>(Wv, Wvh, C * C);
    split_single<<<(C * C / 4 + 255) / 256, 256>>>(Wo, Woh, C * C);

    dim3 blk(NTHREADS);
    dim3 gridProj(C / TILE_N, M / TILE_M, 1);
    dim3 gridS(T / TILE_N, T / TILE_M, B);
    dim3 gridPV(C / TILE_N, T / TILE_M, B);

    // Q = rope(x Wq + bq), K = rope(x Wk + bk), V = x Wv + bv  (fp16 out)
    gemm_h1<true, true,  false, false, 2><<<gridProj, blk, SMEM_TOTAL>>>(
        xh, Wqh, bq, nullptr, Qh, M, C, C, 0, 0, 0, 1.0f);
    gemm_h1<true, true,  false, false, 2><<<gridProj, blk, SMEM_TOTAL>>>(
        xh, Wkh, bk, nullptr, Kh, M, C, C, 0, 0, 0, 1.0f);
    gemm_h1<true, false, false, false, 2><<<gridProj, blk, SMEM_TOTAL>>>(
        xh, Wvh, bv, nullptr, Vh, M, C, C, 0, 0, 0, 1.0f);

    // S = Q K^T / 32 (fp32, causal block skip)
    gemm_h1<false, false, true, false, 0><<<gridS, blk, SMEM_TOTAL>>>(
        Qh, Kh, nullptr, pS, nullptr, T, T, C, sTC, sTC, sTT, 0.03125f);

    softmax_h<<<B * T, 256>>>(pS, Ph, T);

    // O = P V (K truncated at causal boundary), fp16 out
    gemm_h1<true, false, false, true, 2><<<gridPV, blk, SMEM_TOTAL>>>(
        Ph, Vh, nullptr, nullptr, Oh, T, C, T, sTT, sTC, sTC, 1.0f);

    // out = O Wo + bo (fp32)
    gemm_h1<true, false, false, false, 0><<<gridProj, blk, SMEM_TOTAL>>>(
        Oh, Woh, bo, out, nullptr, M, C, C, 0, 0, 0, 1.0f);
}

// round 15
// speedup vs baseline: 2.0743x; 1.0743x over previous
#include <cuda_runtime.h>
#include <cuda_fp16.h>
#include <math.h>
#include <stdint.h>

// ---------------------------------------------------------------------------
// B=4, T=2048, C=1024.  out = softmax(causal(QK^T/32)) V Wo + bo
// Pure fp16 mma.sync (fp32 accum) on every GEMM (error ~6.7e-4 measured).
// R15: MLP-4 splits, single-pass register softmax, merged QKV launch.
// ---------------------------------------------------------------------------
#define BATCH 4
#define SEQ   2048
#define CH    1024
#define MTOT  (BATCH * SEQ)

typedef __half h16;
typedef __half2 h162;

__device__ h16 g_xh[MTOT * CH];
__device__ h16 g_Wqh[CH * CH], g_Wkh[CH * CH], g_Wvh[CH * CH], g_Woh[CH * CH];
__device__ h16 g_Qh[MTOT * CH];
__device__ h16 g_Kh[MTOT * CH];
__device__ h16 g_Vh[MTOT * CH];
__device__ h16 g_Oh[MTOT * CH];
__device__ float g_S[BATCH * SEQ * SEQ];
__device__ h16 g_Ph[BATCH * SEQ * SEQ];

#define TILE_M 128
#define TILE_N 128
#define BK     32
#define NTHREADS 256

#define AROW  80
#define AMAT  10240
#define OFF_AH 0
#define OFF_BH AMAT
#define STAGE  20480
#define NSTAGE 3
#define SMEM_TOTAL (NSTAGE * STAGE)   // 61440

__device__ __forceinline__ uint32_t smem_u32(const void* p) {
    uint32_t a;
    asm("{ .reg .u64 t; cvta.to.shared.u64 t, %1; cvt.u32.u64 %0, t; }" : "=r"(a) : "l"(p));
    return a;
}
#define CP16(dst, src) asm volatile("cp.async.cg.shared.global [%0], [%1], 16;" :: "r"(dst), "l"(src))
#define CP_COMMIT()    asm volatile("cp.async.commit_group;" ::: "memory")
#define CP_WAIT1()     asm volatile("cp.async.wait_group 1;" ::: "memory")

__device__ __forceinline__ void ldsm4(uint32_t* r, uint32_t addr) {
    asm volatile("ldmatrix.sync.aligned.m8n8.x4.shared.b16 {%0,%1,%2,%3}, [%4];"
                 : "=r"(r[0]), "=r"(r[1]), "=r"(r[2]), "=r"(r[3]) : "r"(addr));
}
__device__ __forceinline__ void ldsm4t(uint32_t* r, uint32_t addr) {
    asm volatile("ldmatrix.sync.aligned.m8n8.x4.trans.shared.b16 {%0,%1,%2,%3}, [%4];"
                 : "=r"(r[0]), "=r"(r[1]), "=r"(r[2]), "=r"(r[3]) : "r"(addr));
}
__device__ __forceinline__ void mma16816(float* d, const uint32_t* a, uint32_t b0, uint32_t b1) {
    asm volatile(
        "mma.sync.aligned.m16n8k16.row.col.f32.f16.f16.f32 "
        "{%0,%1,%2,%3},{%4,%5,%6,%7},{%8,%9},{%0,%1,%2,%3};"
        : "+f"(d[0]), "+f"(d[1]), "+f"(d[2]), "+f"(d[3])
        : "r"(a[0]), "r"(a[1]), "r"(a[2]), "r"(a[3]), "r"(b0), "r"(b1));
}

// ---------------------------------------------------------------------------
// fp32 -> fp16, 16 elems/thread, 4 independent float4 loads (MLP=4)
// ---------------------------------------------------------------------------
__global__ void split_single(const float* __restrict__ s, h16* __restrict__ h, int n)
{
    const int base = 16 * (blockIdx.x * blockDim.x + threadIdx.x);
    if (base >= n) return;
    float4 v0 = *reinterpret_cast<const float4*>(s + base);
    float4 v1 = *reinterpret_cast<const float4*>(s + base + 4);
    float4 v2 = *reinterpret_cast<const float4*>(s + base + 8);
    float4 v3 = *reinterpret_cast<const float4*>(s + base + 12);
    h162 o[8];
    o[0] = {__float2half_rn(v0.x), __float2half_rn(v0.y)};
    o[1] = {__float2half_rn(v0.z), __float2half_rn(v0.w)};
    o[2] = {__float2half_rn(v1.x), __float2half_rn(v1.y)};
    o[3] = {__float2half_rn(v1.z), __float2half_rn(v1.w)};
    o[4] = {__float2half_rn(v2.x), __float2half_rn(v2.y)};
    o[5] = {__float2half_rn(v2.z), __float2half_rn(v2.w)};
    o[6] = {__float2half_rn(v3.x), __float2half_rn(v3.y)};
    o[7] = {__float2half_rn(v3.z), __float2half_rn(v3.w)};
    uint4* dst = reinterpret_cast<uint4*>(h + base);
    dst[0] = *reinterpret_cast<uint4*>(&o[0]);
    dst[1] = *reinterpret_cast<uint4*>(&o[4]);
}

// ---------------------------------------------------------------------------
// C = alpha * A @ op(B) (+bias) (+RoPE), fp16 in, fp32 accum.
// ---------------------------------------------------------------------------
template<bool BN, bool ROPE, bool CSKIP, bool CKLIM, int EPI>
__global__ __launch_bounds__(NTHREADS, 1)
void gemm_h1(const h16* __restrict__ Ah, const h16* __restrict__ Bh,
             const float* __restrict__ bias,
             float* __restrict__ Cf, h16* __restrict__ Ch,
             int M, int N, int K,
             long long sA, long long sB, long long sC, float alpha)
{
    constexpr int BROW = BN ? 272 : 80;

    extern __shared__ __align__(256) char smem[];
    const uint32_t sbase = smem_u32(smem);

    const int m0 = blockIdx.y * TILE_M;
    const int n0 = blockIdx.x * TILE_N;
    if (CSKIP && n0 >= m0 + TILE_M) return;

    const h16* Ahb = Ah + (long long)blockIdx.z * sA;
    const h16* Bhb = Bh + (long long)blockIdx.z * sB;

    const int tid = threadIdx.x;
    const int wid = tid >> 5;
    const int lid = tid & 31;
    const int warp_m = wid >> 2;
    const int warp_n = wid & 3;

    const int Kend  = CKLIM ? (m0 + TILE_M) : K;
    const int NITER = Kend / BK;

    float acc[4][4][4];
    #pragma unroll
    for (int i = 0; i < 4; i++)
        #pragma unroll
        for (int j = 0; j < 4; j++)
            #pragma unroll
            for (int k = 0; k < 4; k++) acc[i][j][k] = 0.f;

    auto issue = [&](int it) {
        if (it < NITER) {
            const uint32_t sb = sbase + (it % NSTAGE) * STAGE;
            const int kc = it * BK;
            #pragma unroll
            for (int i = 0; i < 2; ++i) {
                const int c  = tid + i * NTHREADS;
                const int r  = c >> 2;
                const int ch = c & 3;
                const size_t g = (size_t)(m0 + r) * K + kc + ch * 8;
                const uint32_t so = (uint32_t)(r * AROW + ch * 16);
                CP16(sb + OFF_AH + so, Ahb + g);
            }
            if (!BN) {
                #pragma unroll
                for (int i = 0; i < 2; ++i) {
                    const int c  = tid + i * NTHREADS;
                    const int r  = c >> 2;
                    const int ch = c & 3;
                    const size_t g = (size_t)(n0 + r) * K + kc + ch * 8;
                    const uint32_t so = (uint32_t)(r * BROW + ch * 16);
                    CP16(sb + OFF_BH + so, Bhb + g);
                }
            } else {
                #pragma unroll
                for (int i = 0; i < 2; ++i) {
                    const int c  = tid + i * NTHREADS;
                    const int kr = c >> 4;
                    const int ch = c & 15;
                    const size_t g = (size_t)(kc + kr) * N + n0 + ch * 8;
                    const uint32_t so = (uint32_t)(kr * BROW + ch * 16);
                    CP16(sb + OFF_BH + so, Bhb + g);
                }
            }
        }
        CP_COMMIT();
    };

    const int a_r = (lid & 15);
    const int a_c = (lid >> 4) << 3;
    const int b_r = (lid & 7) + ((lid >> 4) << 3);
    const int b_c = ((lid >> 3) & 1) << 3;
    const int t_k = (lid & 7) + (((lid >> 3) & 1) << 3);
    const int t_n = (lid >> 4) << 3;

    issue(0);
    issue(1);

    for (int it = 0; it < NITER; ++it) {
        CP_WAIT1();
        __syncthreads();
        const uint32_t sstage = sbase + (it % NSTAGE) * STAGE;

        #pragma unroll
        for (int kk = 0; kk < BK; kk += 16) {
            uint32_t ah[16], bh[8];
            #pragma unroll
            for (int mt = 0; mt < 4; ++mt) {
                const uint32_t addr = sstage + OFF_AH +
                    (uint32_t)((warp_m * 64 + mt * 16 + a_r) * AROW + (kk + a_c) * 2);
                ldsm4(ah + mt * 4, addr);
            }
            if (!BN) {
                #pragma unroll
                for (int nt = 0; nt < 2; ++nt) {
                    const uint32_t addr = sstage + OFF_BH +
                        (uint32_t)((warp_n * 32 + nt * 16 + b_r) * BROW + (kk + b_c) * 2);
                    ldsm4(bh + nt * 4, addr);
                }
            } else {
                #pragma unroll
                for (int p = 0; p < 2; ++p) {
                    const uint32_t addr = sstage + OFF_BH +
                        (uint32_t)((kk + t_k) * BROW + (warp_n * 32 + p * 16 + t_n) * 2);
                    ldsm4t(bh + p * 4, addr);
                }
            }
            #pragma unroll
            for (int mt = 0; mt < 4; ++mt)
                #pragma unroll
                for (int nt = 0; nt < 4; ++nt) {
                    const uint32_t* bhp = &bh[(nt >> 1) * 4 + (nt & 1) * 2];
                    mma16816(acc[mt][nt], ah + mt * 4, bhp[0], bhp[1]);
                }
        }
        issue(it + 2);
    }

    // ---- epilogue ----
    const int mbase = m0 + warp_m * 64 + (lid >> 2);
    const int nbase = n0 + warp_n * 32 + (lid & 3) * 2;

    float binv[4];
    #pragma unroll
    for (int nt = 0; nt < 4; ++nt)
        if (ROPE) binv[nt] = powf(10000.0f, -(float)(nbase + nt * 8) / (float)N);

    #pragma unroll
    for (int mt = 0; mt < 4; ++mt) {
        #pragma unroll
        for (int h = 0; h < 2; ++h) {
            const int m = mbase + mt * 16 + h * 8;
            const int t = m & (SEQ - 1);
            #pragma unroll
            for (int nt = 0; nt < 4; ++nt) {
                const int n = nbase + nt * 8;
                float v0 = acc[mt][nt][h * 2 + 0] * alpha;
                float v1 = acc[mt][nt][h * 2 + 1] * alpha;
                if (bias) { v0 += bias[n]; v1 += bias[n + 1]; }
                if (ROPE) {
                    float s, co;
                    sincosf((float)t * binv[nt], &s, &co);
                    const float x0 = v0, x1 = v1;
                    v0 = x0 * co - x1 * s;
                    v1 = x1 * co + x0 * s;
                }
                const size_t off = (size_t)m * N + n + (size_t)blockIdx.z * sC;
                if (EPI == 2) {
                    *reinterpret_cast<h162*>(Ch + off) =
                        {__float2half_rn(v0), __float2half_rn(v1)};
                } else {
                    *reinterpret_cast<float2*>(Cf + off) = make_float2(v0, v1);
                }
            }
        }
    }
}

// ---------------------------------------------------------------------------
// Merged QKV projection: grid (24, 64); blockIdx.x>>3 selects matrix.
// B n-major [K,N] (ldmatrix.trans), fp16 out, runtime RoPE flag.
// ---------------------------------------------------------------------------
__global__ __launch_bounds__(NTHREADS, 1)
void gemm_qkv(const h16* __restrict__ xh,
              const h16* __restrict__ Wq, const h16* __restrict__ Wk,
              const h16* __restrict__ Wv,
              const float* __restrict__ bq, const float* __restrict__ bk,
              const float* __restrict__ bv,
              h16* __restrict__ Q, h16* __restrict__ K16, h16* __restrict__ V)
{
    constexpr int BROW = 272;
    const int M = MTOT, N = CH, K = CH;

    extern __shared__ __align__(256) char smem[];
    const uint32_t sbase = smem_u32(smem);

    const int which = blockIdx.x >> 3;
    const int n0 = (blockIdx.x & 7) * TILE_N;
    const int m0 = blockIdx.y * TILE_M;
    const h16* Bhb = which == 0 ? Wq : which == 1 ? Wk : Wv;
    const float* bias = which == 0 ? bq : which == 1 ? bk : bv;
    h16* Ch = which == 0 ? Q : which == 1 ? K16 : V;
    const bool rope = (which < 2);

    const int tid = threadIdx.x;
    const int wid = tid >> 5;
    const int lid = tid & 31;
    const int warp_m = wid >> 2;
    const int warp_n = wid & 3;

    const int NITER = K / BK;

    float acc[4][4][4];
    #pragma unroll
    for (int i = 0; i < 4; i++)
        #pragma unroll
        for (int j = 0; j < 4; j++)
            #pragma unroll
            for (int k = 0; k < 4; k++) acc[i][j][k] = 0.f;

    auto issue = [&](int it) {
        if (it < NITER) {
            const uint32_t sb = sbase + (it % NSTAGE) * STAGE;
            const int kc = it * BK;
            #pragma unroll
            for (int i = 0; i < 2; ++i) {
                const int c  = tid + i * NTHREADS;
                const int r  = c >> 2;
                const int ch = c & 3;
                const size_t g = (size_t)(m0 + r) * K + kc + ch * 8;
                const uint32_t so = (uint32_t)(r * AROW + ch * 16);
                CP16(sb + OFF_AH + so, xh + g);
            }
            #pragma unroll
            for (int i = 0; i < 2; ++i) {
                const int c  = tid + i * NTHREADS;
                const int kr = c >> 4;
                const int ch = c & 15;
                const size_t g = (size_t)(kc + kr) * N + n0 + ch * 8;
                const uint32_t so = (uint32_t)(kr * BROW + ch * 16);
                CP16(sb + OFF_BH + so, Bhb + g);
            }
        }
        CP_COMMIT();
    };

    const int a_r = (lid & 15);
    const int a_c = (lid >> 4) << 3;
    const int t_k = (lid & 7) + (((lid >> 3) & 1) << 3);
    const int t_n = (lid >> 4) << 3;

    issue(0);
    issue(1);

    for (int it = 0; it < NITER; ++it) {
        CP_WAIT1();
        __syncthreads();
        const uint32_t sstage = sbase + (it % NSTAGE) * STAGE;

        #pragma unroll
        for (int kk = 0; kk < BK; kk += 16) {
            uint32_t ah[16], bh[8];
            #pragma unroll
            for (int mt = 0; mt < 4; ++mt) {
                const uint32_t addr = sstage + OFF_AH +
                    (uint32_t)((warp_m * 64 + mt * 16 + a_r) * AROW + (kk + a_c) * 2);
                ldsm4(ah + mt * 4, addr);
            }
            #pragma unroll
            for (int p = 0; p < 2; ++p) {
                const uint32_t addr = sstage + OFF_BH +
                    (uint32_t)((kk + t_k) * BROW + (warp_n * 32 + p * 16 + t_n) * 2);
                ldsm4t(bh + p * 4, addr);
            }
            #pragma unroll
            for (int mt = 0; mt < 4; ++mt)
                #pragma unroll
                for (int nt = 0; nt < 4; ++nt) {
                    const uint32_t* bhp = &bh[(nt >> 1) * 4 + (nt & 1) * 2];
                    mma16816(acc[mt][nt], ah + mt * 4, bhp[0], bhp[1]);
                }
        }
        issue(it + 2);
    }

    const int mbase = m0 + warp_m * 64 + (lid >> 2);
    const int nbase = n0 + warp_n * 32 + (lid & 3) * 2;

    float binv[4];
    #pragma unroll
    for (int nt = 0; nt < 4; ++nt)
        if (rope) binv[nt] = powf(10000.0f, -(float)(nbase + nt * 8) / (float)N);

    #pragma unroll
    for (int mt = 0; mt < 4; ++mt) {
        #pragma unroll
        for (int h = 0; h < 2; ++h) {
            const int m = mbase + mt * 16 + h * 8;
            const int t = m & (SEQ - 1);
            #pragma unroll
            for (int nt = 0; nt < 4; ++nt) {
                const int n = nbase + nt * 8;
                float v0 = acc[mt][nt][h * 2 + 0] + bias[n];
                float v1 = acc[mt][nt][h * 2 + 1] + bias[n + 1];
                if (rope) {
                    float s, co;
                    sincosf((float)t * binv[nt], &s, &co);
                    const float x0 = v0, x1 = v1;
                    v0 = x0 * co - x1 * s;
                    v1 = x1 * co + x0 * s;
                }
                *reinterpret_cast<h162*>(Ch + (size_t)m * N + n) =
                    {__float2half_rn(v0), __float2half_rn(v1)};
            }
        }
    }
}

// ---------------------------------------------------------------------------
// Single-pass causal softmax: row held in registers (<=8 floats/thread).
// fp32 S (read once) -> fp16 P; stores only up to the causal 128 boundary.
// ---------------------------------------------------------------------------
__global__ __launch_bounds__(256)
void softmax_h(const float* __restrict__ S, h16* __restrict__ Ph, int T)
{
    const long long row = blockIdx.x;
    const int t = (int)(row % T);
    const float* s = S + row * (long long)T;
    h16* ph = Ph + row * (long long)T;
    const int len  = t + 1;
    const int zlim = ((t >> 7) + 1) << 7;
    const int tid = threadIdx.x;
    const int b0 = tid * 4;           // chunk in [0, 1024)
    const int b1 = 1024 + tid * 4;    // chunk in [1024, 2048)

    float v[8];
    {   // masked loads (S memory is always valid across full row)
        float4 a = *reinterpret_cast<const float4*>(s + b0);
        v[0] = a.x; v[1] = a.y; v[2] = a.z; v[3] = a.w;
        if (b1 < zlim) {
            float4 b = *reinterpret_cast<const float4*>(s + b1);
            v[4] = b.x; v[5] = b.y; v[6] = b.z; v[7] = b.w;
        } else {
            v[4] = v[5] = v[6] = v[7] = -3.0e38f;
        }
        #pragma unroll
        for (int j = 0; j < 4; ++j) if (b0 + j >= len) v[j] = -3.0e38f;
        #pragma unroll
        for (int j = 0; j < 4; ++j) if (b1 + j >= len) v[4 + j] = -3.0e38f;
    }

    __shared__ float sh[8];
    __shared__ float bcast;

    float mx = -3.0e38f;
    #pragma unroll
    for (int j = 0; j < 8; ++j) mx = fmaxf(mx, v[j]);
    #pragma unroll
    for (int o = 16; o > 0; o >>= 1) mx = fmaxf(mx, __shfl_xor_sync(0xffffffffu, mx, o));
    if ((tid & 31) == 0) sh[tid >> 5] = mx;
    __syncthreads();
    if (tid == 0) {
        float m = sh[0];
        #pragma unroll
        for (int i = 1; i < 8; i++) m = fmaxf(m, sh[i]);
        bcast = m;
    }
    __syncthreads();
    mx = bcast;

    float sum = 0.f;
    #pragma unroll
    for (int j = 0; j < 8; ++j) {
        v[j] = (v[j] > -1.0e38f) ? expf(v[j] - mx) : 0.f;
        sum += v[j];
    }
    #pragma unroll
    for (int o = 16; o > 0; o >>= 1) sum += __shfl_xor_sync(0xffffffffu, sum, o);
    __syncthreads();
    if ((tid & 31) == 0) sh[tid >> 5] = sum;
    __syncthreads();
    if (tid == 0) {
        float acc = 0.f;
        #pragma unroll
        for (int i = 0; i < 8; i++) acc += sh[i];
        bcast = acc;
    }
    __syncthreads();
    const float invs = 1.0f / bcast;

    if (b0 < zlim) {
        h162 o0 = {__float2half_rn(v[0] * invs), __float2half_rn(v[1] * invs)};
        h162 o1 = {__float2half_rn(v[2] * invs), __float2half_rn(v[3] * invs)};
        h162 pair[2] = {o0, o1};
        *reinterpret_cast<uint2*>(ph + b0) = *reinterpret_cast<uint2*>(pair);
    }
    if (b1 < zlim) {
        h162 o0 = {__float2half_rn(v[4] * invs), __float2half_rn(v[5] * invs)};
        h162 o1 = {__float2half_rn(v[6] * invs), __float2half_rn(v[7] * invs)};
        h162 pair[2] = {o0, o1};
        *reinterpret_cast<uint2*>(ph + b1) = *reinterpret_cast<uint2*>(pair);
    }
}

// ---------------------------------------------------------------------------
// kernel_launch: x, Wq, bq, Wk, bk, Wv, bv, Wo, bo
// ---------------------------------------------------------------------------
extern "C" void kernel_launch(void* const* d_in, const int* in_sizes, int n_in,
                              void* d_out, int out_size)
{
    const float* x  = (const float*)d_in[0];
    const float* Wq = (const float*)d_in[1];
    const float* bq = (const float*)d_in[2];
    const float* Wk = (const float*)d_in[3];
    const float* bk = (const float*)d_in[4];
    const float* Wv = (const float*)d_in[5];
    const float* bv = (const float*)d_in[6];
    const float* Wo = (const float*)d_in[7];
    const float* bo = (const float*)d_in[8];
    float* out = (float*)d_out;

    h16 *xh, *Wqh, *Wkh, *Wvh, *Woh;
    h16 *Qh, *Kh, *Vh, *Oh, *Ph;
    float* pS;
    cudaGetSymbolAddress((void**)&xh, g_xh);
    cudaGetSymbolAddress((void**)&Wqh, g_Wqh); cudaGetSymbolAddress((void**)&Wkh, g_Wkh);
    cudaGetSymbolAddress((void**)&Wvh, g_Wvh); cudaGetSymbolAddress((void**)&Woh, g_Woh);
    cudaGetSymbolAddress((void**)&Qh, g_Qh);
    cudaGetSymbolAddress((void**)&Kh, g_Kh);
    cudaGetSymbolAddress((void**)&Vh, g_Vh);
    cudaGetSymbolAddress((void**)&Oh, g_Oh);
    cudaGetSymbolAddress((void**)&Ph, g_Ph);
    cudaGetSymbolAddress((void**)&pS, g_S);

    const int B = BATCH, T = SEQ, C = CH, M = MTOT;
    const long long sTC = (long long)T * C;
    const long long sTT = (long long)T * T;

    cudaFuncSetAttribute(gemm_qkv, cudaFuncAttributeMaxDynamicSharedMemorySize, SMEM_TOTAL);
    cudaFuncSetAttribute(gemm_h1<false, false, true,  false, 0>, cudaFuncAttributeMaxDynamicSharedMemorySize, SMEM_TOTAL);
    cudaFuncSetAttribute(gemm_h1<true,  false, false, true,  2>, cudaFuncAttributeMaxDynamicSharedMemorySize, SMEM_TOTAL);
    cudaFuncSetAttribute(gemm_h1<true,  false, false, false, 0>, cudaFuncAttributeMaxDynamicSharedMemorySize, SMEM_TOTAL);

    split_single<<<(M * C / 16 + 255) / 256, 256>>>(x, xh, M * C);
    split_single<<<(C * C / 16 + 255) / 256, 256>>>(Wq, Wqh, C * C);
    split_single<<<(C * C / 16 + 255) / 256, 256>>>(Wk, Wkh, C * C);
    split_single<<<(C * C / 16 + 255) / 256, 256>>>(Wv, Wvh, C * C);
    split_single<<<(C * C / 16 + 255) / 256, 256>>>(Wo, Woh, C * C);

    dim3 blk(NTHREADS);
    dim3 gridQKV(3 * (C / TILE_N), M / TILE_M);   // 24 x 64
    dim3 gridProj(C / TILE_N, M / TILE_M, 1);
    dim3 gridS(T / TILE_N, T / TILE_M, B);
    dim3 gridPV(C / TILE_N, T / TILE_M, B);

    // Q/K/V in one launch (RoPE on Q,K)
    gemm_qkv<<<gridQKV, blk, SMEM_TOTAL>>>(xh, Wqh, Wkh, Wvh, bq, bk, bv, Qh, Kh, Vh);

    // S = Q K^T / 32 (fp32, causal block skip)
    gemm_h1<false, false, true, false, 0><<<gridS, blk, SMEM_TOTAL>>>(
        Qh, Kh, nullptr, pS, nullptr, T, T, C, sTC, sTC, sTT, 0.03125f);

    softmax_h<<<B * T, 256>>>(pS, Ph, T);

    // O = P V (K truncated at causal boundary), fp16 out
    gemm_h1<true, false, false, true, 2><<<gridPV, blk, SMEM_TOTAL>>>(
        Ph, Vh, nullptr, nullptr, Oh, T, C, T, sTT, sTC, sTC, 1.0f);

    // out = O Wo + bo (fp32)
    gemm_h1<true, false, false, false, 0><<<gridProj, blk, SMEM_TOTAL>>>(
        Oh, Woh, bo, out, nullptr, M, C, C, 0, 0, 0, 1.0f);
}